// round 1
// baseline (speedup 1.0000x reference)
#include <cuda_runtime.h>
#include <cstdint>

#define NH 12
#define DH 64
#define SEQ 512
#define DM 768
#define MAXB 32

// Scratch: Q,K,V in [B,H,S,DH] layout
__device__ float g_q[(size_t)MAXB * NH * SEQ * DH];
__device__ float g_k[(size_t)MAXB * NH * SEQ * DH];
__device__ float g_v[(size_t)MAXB * NH * SEQ * DH];

// ---------------------------------------------------------------------------
// Kernel 1: fused QKV projection.
// C[M, 2304] = A[M,768] @ [Wq|Wk|Wv], + bias, scattered into g_q/g_k/g_v
// Tile: BM=128, BN=64, BK=16. 256 threads, 8x4 micro-tile per thread.
// ---------------------------------------------------------------------------
__global__ __launch_bounds__(256) void qkv_gemm_kernel(
    const float* __restrict__ A,
    const float* __restrict__ Wq, const float* __restrict__ bq,
    const float* __restrict__ Wk, const float* __restrict__ bk,
    const float* __restrict__ Wv, const float* __restrict__ bv)
{
    __shared__ float Ash[16][132];   // [k][m], padded (132%4==0 keeps float4 alignment)
    __shared__ float Bsh[16][68];    // [k][n], padded

    const int bm = blockIdx.y * 128;
    const int gn = blockIdx.x * 64;      // 0..2303
    const int mi = gn / DM;              // 0=Q,1=K,2=V
    const int n0 = gn - mi * DM;         // column within the 768-wide matrix

    const float* W    = (mi == 0) ? Wq : ((mi == 1) ? Wk : Wv);
    const float* bias = (mi == 0) ? bq : ((mi == 1) ? bk : bv);
    float* dst        = (mi == 0) ? g_q : ((mi == 1) ? g_k : g_v);

    const int tid = threadIdx.x;
    const int tx = tid & 15;      // 0..15 -> cols tx*4
    const int ty = tid >> 4;      // 0..15 -> rows ty*8

    float acc[8][4];
#pragma unroll
    for (int i = 0; i < 8; i++)
#pragma unroll
        for (int j = 0; j < 4; j++) acc[i][j] = 0.0f;

    const int ar = tid >> 2;           // 0..63  (rows ar, ar+64)
    const int ac = (tid & 3) * 4;      // 0,4,8,12
    const int br = tid >> 4;           // 0..15
    const int bc = (tid & 15) * 4;     // 0..60

    for (int k0 = 0; k0 < DM; k0 += 16) {
        float4 a0 = *(const float4*)(A + (size_t)(bm + ar)       * DM + k0 + ac);
        float4 a1 = *(const float4*)(A + (size_t)(bm + ar + 64)  * DM + k0 + ac);
        float4 b0 = *(const float4*)(W + (size_t)(k0 + br)       * DM + n0 + bc);

        __syncthreads();   // previous iteration done reading smem
        Ash[ac + 0][ar] = a0.x; Ash[ac + 1][ar] = a0.y;
        Ash[ac + 2][ar] = a0.z; Ash[ac + 3][ar] = a0.w;
        Ash[ac + 0][ar + 64] = a1.x; Ash[ac + 1][ar + 64] = a1.y;
        Ash[ac + 2][ar + 64] = a1.z; Ash[ac + 3][ar + 64] = a1.w;
        *(float4*)&Bsh[br][bc] = b0;
        __syncthreads();

#pragma unroll
        for (int k = 0; k < 16; k++) {
            float4 av0 = *(const float4*)&Ash[k][ty * 8];
            float4 av1 = *(const float4*)&Ash[k][ty * 8 + 4];
            float4 bv4 = *(const float4*)&Bsh[k][tx * 4];
            float a[8] = {av0.x, av0.y, av0.z, av0.w, av1.x, av1.y, av1.z, av1.w};
            float b[4] = {bv4.x, bv4.y, bv4.z, bv4.w};
#pragma unroll
            for (int i = 0; i < 8; i++)
#pragma unroll
                for (int j = 0; j < 4; j++)
                    acc[i][j] = fmaf(a[i], b[j], acc[i][j]);
        }
    }

    // Scatter-write into [B, H, S, DH]
#pragma unroll
    for (int i = 0; i < 8; i++) {
        int m = bm + ty * 8 + i;
        int b = m >> 9;            // /512
        int s = m & 511;
#pragma unroll
        for (int j = 0; j < 4; j++) {
            int c = n0 + tx * 4 + j;
            int h = c >> 6;
            int d = c & 63;
            dst[(((size_t)(b * NH + h)) * SEQ + s) * DH + d] = acc[i][j] + bias[c];
        }
    }
}

// ---------------------------------------------------------------------------
// Kernel 2: fused power-law attention for one (b, h, 64-row q-tile).
// Streaming over 32-row K/V tiles:
//   u = (q.k/8 + 5)^2 ; den += u ; acc += u * (mask_k * v_k)
// ctx = acc / (den + 1e-10)   (mask applied AFTER normalization -> only on V)
// ---------------------------------------------------------------------------
__global__ __launch_bounds__(256) void attn_kernel(
    const float* __restrict__ mask,    // [B, S]
    float* __restrict__ out)           // [B, S, 768]
{
    __shared__ float Qs[64][65];
    __shared__ float Ks[32][65];
    __shared__ float Vs[32][64];       // mask pre-multiplied; stride 64 for float4
    __shared__ float Us[64][33];

    const int b  = blockIdx.z;
    const int h  = blockIdx.y;
    const int qt = blockIdx.x * 64;

    const float* Qg = g_q + (((size_t)(b * NH + h)) * SEQ + qt) * DH;
    const float* Kg = g_k + ((size_t)(b * NH + h)) * SEQ * DH;
    const float* Vg = g_v + ((size_t)(b * NH + h)) * SEQ * DH;

    const int tid = threadIdx.x;

    // Load Q tile (64x64): thread -> row tid/4, cols (tid%4)*16 .. +15
    {
        int r  = tid >> 2;
        int c0 = (tid & 3) * 16;
#pragma unroll
        for (int u = 0; u < 4; u++) {
            float4 qv = *(const float4*)(Qg + (size_t)r * DH + c0 + u * 4);
            Qs[r][c0 + u * 4 + 0] = qv.x;
            Qs[r][c0 + u * 4 + 1] = qv.y;
            Qs[r][c0 + u * 4 + 2] = qv.z;
            Qs[r][c0 + u * 4 + 3] = qv.w;
        }
    }

    // Phase-1 mapping: 32x8 thread grid, each computes 2 rows x 4 cols of scores
    const int p1r = (tid >> 3) * 2;     // 0,2,..,62
    const int p1c = (tid & 7) * 4;      // 0,4,..,28

    // Phase-2 mapping: row tid/4, dim group (tid%4)*16
    const int row2 = tid >> 2;
    const int tg   = tid & 3;

    float accv[16];
#pragma unroll
    for (int j = 0; j < 16; j++) accv[j] = 0.0f;
    float den = 0.0f;

    for (int kt = 0; kt < SEQ; kt += 32) {
        // Load K,V tile (32x64): thread -> row tid/8, cols (tid%8)*8 .. +7
        int r = tid >> 3;
        int c = (tid & 7) * 8;
        float4 k0 = *(const float4*)(Kg + (size_t)(kt + r) * DH + c);
        float4 k1 = *(const float4*)(Kg + (size_t)(kt + r) * DH + c + 4);
        float4 v0 = *(const float4*)(Vg + (size_t)(kt + r) * DH + c);
        float4 v1 = *(const float4*)(Vg + (size_t)(kt + r) * DH + c + 4);
        float mv  = mask[(size_t)b * SEQ + kt + r];

        __syncthreads();   // previous phase-2 done with Us/Vs; iter0: Qs visible
        Ks[r][c + 0] = k0.x; Ks[r][c + 1] = k0.y; Ks[r][c + 2] = k0.z; Ks[r][c + 3] = k0.w;
        Ks[r][c + 4] = k1.x; Ks[r][c + 5] = k1.y; Ks[r][c + 6] = k1.z; Ks[r][c + 7] = k1.w;
        *(float4*)&Vs[r][c]     = make_float4(v0.x * mv, v0.y * mv, v0.z * mv, v0.w * mv);
        *(float4*)&Vs[r][c + 4] = make_float4(v1.x * mv, v1.y * mv, v1.z * mv, v1.w * mv);
        __syncthreads();

        // Phase 1: scores -> u = (s*0.125 + 5)^2 into Us
        float sc[2][4];
#pragma unroll
        for (int i = 0; i < 2; i++)
#pragma unroll
            for (int j = 0; j < 4; j++) sc[i][j] = 0.0f;

#pragma unroll 8
        for (int k = 0; k < 64; k++) {
            float q0 = Qs[p1r][k];
            float q1 = Qs[p1r + 1][k];
#pragma unroll
            for (int j = 0; j < 4; j++) {
                float kv = Ks[p1c + j][k];
                sc[0][j] = fmaf(q0, kv, sc[0][j]);
                sc[1][j] = fmaf(q1, kv, sc[1][j]);
            }
        }
#pragma unroll
        for (int i = 0; i < 2; i++)
#pragma unroll
            for (int j = 0; j < 4; j++) {
                float t = fmaf(sc[i][j], 0.125f, 5.0f);
                Us[p1r + i][p1c + j] = t * t;
            }
        __syncthreads();

        // Phase 2: acc += u * Vmasked ; den += u
#pragma unroll
        for (int kk = 0; kk < 32; kk++) {
            float u = Us[row2][kk];
            den += u;
            const float* vrow = &Vs[kk][tg * 16];
            float4 w0 = *(const float4*)(vrow + 0);
            float4 w1 = *(const float4*)(vrow + 4);
            float4 w2 = *(const float4*)(vrow + 8);
            float4 w3 = *(const float4*)(vrow + 12);
            accv[0]  = fmaf(u, w0.x, accv[0]);  accv[1]  = fmaf(u, w0.y, accv[1]);
            accv[2]  = fmaf(u, w0.z, accv[2]);  accv[3]  = fmaf(u, w0.w, accv[3]);
            accv[4]  = fmaf(u, w1.x, accv[4]);  accv[5]  = fmaf(u, w1.y, accv[5]);
            accv[6]  = fmaf(u, w1.z, accv[6]);  accv[7]  = fmaf(u, w1.w, accv[7]);
            accv[8]  = fmaf(u, w2.x, accv[8]);  accv[9]  = fmaf(u, w2.y, accv[9]);
            accv[10] = fmaf(u, w2.z, accv[10]); accv[11] = fmaf(u, w2.w, accv[11]);
            accv[12] = fmaf(u, w3.x, accv[12]); accv[13] = fmaf(u, w3.y, accv[13]);
            accv[14] = fmaf(u, w3.z, accv[14]); accv[15] = fmaf(u, w3.w, accv[15]);
        }
        // next iteration's first __syncthreads protects Us/Vs reuse
    }

    float inv = 1.0f / (den + 1e-10f);
    float* o = out + ((size_t)b * SEQ + qt + row2) * DM + h * DH + tg * 16;
#pragma unroll
    for (int j = 0; j < 16; j++) o[j] = accv[j] * inv;
}

// ---------------------------------------------------------------------------
extern "C" void kernel_launch(void* const* d_in, const int* in_sizes, int n_in,
                              void* d_out, int out_size)
{
    const float* hidden = (const float*)d_in[0];
    const float* mask   = (const float*)d_in[1];
    const float* Wq     = (const float*)d_in[2];
    const float* bq     = (const float*)d_in[3];
    const float* Wk     = (const float*)d_in[4];
    const float* bk     = (const float*)d_in[5];
    const float* Wv     = (const float*)d_in[6];
    const float* bv     = (const float*)d_in[7];
    float* out = (float*)d_out;

    const int BS = in_sizes[1];        // mask has B*S elements
    const int B  = BS / SEQ;
    const int M  = BS;                 // GEMM M dimension

    dim3 g1(3 * DM / 64, M / 128);     // (36, 128) for B=32
    qkv_gemm_kernel<<<g1, 256>>>(hidden, Wq, bq, Wk, bk, Wv, bv);

    dim3 g2(SEQ / 64, NH, B);          // (8, 12, B)
    attn_kernel<<<g2, 256>>>(mask, out);
}

// round 2
// speedup vs baseline: 1.0175x; 1.0175x over previous
#include <cuda_runtime.h>
#include <cstdint>

#define NH 12
#define DH 64
#define SEQ 512
#define DM 768
#define MAXB 32

typedef unsigned long long u64;

// ---- f32x2 packed helpers (sm_103a FFMA2 path, only reachable via PTX) ----
__device__ __forceinline__ u64 ffma2(u64 a, u64 b, u64 c) {
    u64 d;
    asm("fma.rn.f32x2 %0, %1, %2, %3;" : "=l"(d) : "l"(a), "l"(b), "l"(c));
    return d;
}
__device__ __forceinline__ u64 dup2(float x) {
    u64 r;
    asm("mov.b64 %0, {%1, %1};" : "=l"(r) : "f"(x));
    return r;
}
__device__ __forceinline__ u64 pk2(float lo, float hi) {
    u64 r;
    asm("mov.b64 %0, {%1, %2};" : "=l"(r) : "f"(lo), "f"(hi));
    return r;
}
__device__ __forceinline__ float2 unpk(u64 p) {
    float2 f;
    asm("mov.b64 {%0, %1}, %2;" : "=f"(f.x), "=f"(f.y) : "l"(p));
    return f;
}

// Scratch: Q,K,V in [B,H,S,DH] layout
__device__ float g_q[(size_t)MAXB * NH * SEQ * DH];
__device__ float g_k[(size_t)MAXB * NH * SEQ * DH];
__device__ float g_v[(size_t)MAXB * NH * SEQ * DH];

// ---------------------------------------------------------------------------
// Kernel 1: fused QKV projection with f32x2 packed FMA.
// C[M, 2304] = A[M,768] @ [Wq|Wk|Wv], + bias, scattered into g_q/g_k/g_v
// BM=128, BN=64, BK=16. 256 threads. Per thread: 8(m) x 4(n), m packed in pairs.
// ---------------------------------------------------------------------------
__global__ __launch_bounds__(256) void qkv_gemm_kernel(
    const float* __restrict__ A,
    const float* __restrict__ Wq, const float* __restrict__ bq,
    const float* __restrict__ Wk, const float* __restrict__ bk,
    const float* __restrict__ Wv, const float* __restrict__ bv)
{
    __shared__ float Ash[16][132];   // [k][m] transposed; m-pairs contiguous
    __shared__ float Bsh[16][68];    // [k][n]

    const int bm = blockIdx.y * 128;
    const int gn = blockIdx.x * 64;
    const int mi = gn / DM;              // 0=Q,1=K,2=V
    const int n0 = gn - mi * DM;

    const float* W    = (mi == 0) ? Wq : ((mi == 1) ? Wk : Wv);
    const float* bias = (mi == 0) ? bq : ((mi == 1) ? bk : bv);
    float* dst        = (mi == 0) ? g_q : ((mi == 1) ? g_k : g_v);

    const int tid = threadIdx.x;
    const int tx = tid & 15;      // n-group: cols tx*4
    const int ty = tid >> 4;      // m-group: rows ty*8

    u64 acc2[4][4];               // [m-pair][n] ; pair = rows ty*8+2ip, +2ip+1
#pragma unroll
    for (int i = 0; i < 4; i++)
#pragma unroll
        for (int j = 0; j < 4; j++) acc2[i][j] = 0ULL;

    const int ar = tid >> 2;
    const int ac = (tid & 3) * 4;
    const int br = tid >> 4;
    const int bc = (tid & 15) * 4;

    for (int k0 = 0; k0 < DM; k0 += 16) {
        float4 a0 = *(const float4*)(A + (size_t)(bm + ar)      * DM + k0 + ac);
        float4 a1 = *(const float4*)(A + (size_t)(bm + ar + 64) * DM + k0 + ac);
        float4 b0 = *(const float4*)(W + (size_t)(k0 + br)      * DM + n0 + bc);

        __syncthreads();
        Ash[ac + 0][ar] = a0.x; Ash[ac + 1][ar] = a0.y;
        Ash[ac + 2][ar] = a0.z; Ash[ac + 3][ar] = a0.w;
        Ash[ac + 0][ar + 64] = a1.x; Ash[ac + 1][ar + 64] = a1.y;
        Ash[ac + 2][ar + 64] = a1.z; Ash[ac + 3][ar + 64] = a1.w;
        *(float4*)&Bsh[br][bc] = b0;
        __syncthreads();

#pragma unroll
        for (int k = 0; k < 16; k++) {
            u64 ap[4];
#pragma unroll
            for (int ip = 0; ip < 4; ip++)
                ap[ip] = *(const u64*)&Ash[k][ty * 8 + 2 * ip];   // 8B aligned
            float4 bv4 = *(const float4*)&Bsh[k][tx * 4];
            u64 bd[4] = {dup2(bv4.x), dup2(bv4.y), dup2(bv4.z), dup2(bv4.w)};
#pragma unroll
            for (int ip = 0; ip < 4; ip++)
#pragma unroll
                for (int j = 0; j < 4; j++)
                    acc2[ip][j] = ffma2(ap[ip], bd[j], acc2[ip][j]);
        }
    }

    // Scatter-write into [B, H, S, DH]
#pragma unroll
    for (int ip = 0; ip < 4; ip++) {
        int m0 = bm + ty * 8 + 2 * ip;
        int b0i = m0 >> 9, s0 = m0 & 511;
        int m1 = m0 + 1;
        int b1i = m1 >> 9, s1 = m1 & 511;
#pragma unroll
        for (int j = 0; j < 4; j++) {
            int c = n0 + tx * 4 + j;
            int h = c >> 6, d = c & 63;
            float2 v = unpk(acc2[ip][j]);
            float bb = bias[c];
            dst[(((size_t)(b0i * NH + h)) * SEQ + s0) * DH + d] = v.x + bb;
            dst[(((size_t)(b1i * NH + h)) * SEQ + s1) * DH + d] = v.y + bb;
        }
    }
}

// ---------------------------------------------------------------------------
// Kernel 2: fused power-law attention, f32x2 packed.
//   u = (q.k/8 + 5)^2 ; den += u ; acc += u * (mask_k * v_k)
//   ctx = acc / (den + 1e-10)
// Q-tile 64 rows, K-tile 32 keys, 256 threads.
// ---------------------------------------------------------------------------
__global__ __launch_bounds__(256) void attn_kernel(
    const float* __restrict__ mask,    // [B, S]
    float* __restrict__ out)           // [B, S, 768]
{
    __shared__ float Qs[64][68];
    __shared__ float Ks[32][68];
    __shared__ float Vs[32][64];       // mask pre-multiplied
    __shared__ float Us[64][34];

    const int b  = blockIdx.z;
    const int h  = blockIdx.y;
    const int qt = blockIdx.x * 64;

    const float* Qg = g_q + (((size_t)(b * NH + h)) * SEQ + qt) * DH;
    const float* Kg = g_k + ((size_t)(b * NH + h)) * SEQ * DH;
    const float* Vg = g_v + ((size_t)(b * NH + h)) * SEQ * DH;

    const int tid = threadIdx.x;

    // Load Q tile (64x64)
    {
        int r  = tid >> 2;
        int c0 = (tid & 3) * 16;
#pragma unroll
        for (int u = 0; u < 4; u++) {
            float4 qv = *(const float4*)(Qg + (size_t)r * DH + c0 + u * 4);
            *(float4*)&Qs[r][c0 + u * 4] = qv;
        }
    }

    // Phase-1 mapping: 2 rows x 4 cols per thread
    const int p1r = (tid >> 3) * 2;     // 0..62
    const int p1c = (tid & 7) * 4;      // 0..28

    // Phase-2 mapping: 2 rows x (4 + 4) d-cols per thread
    const int rp = tid >> 3;            // rows rp*2, rp*2+1
    const int dA = (tid & 7) * 4;       // d chunk A
    const int dB = dA + 32;             // d chunk B

    u64 accA[2][2], accB[2][2];         // [row][d-pair]
#pragma unroll
    for (int i = 0; i < 2; i++)
#pragma unroll
        for (int j = 0; j < 2; j++) { accA[i][j] = 0ULL; accB[i][j] = 0ULL; }
    float den0 = 0.0f, den1 = 0.0f;

    for (int kt = 0; kt < SEQ; kt += 32) {
        // Load K,V tile (32x64)
        int r = tid >> 3;
        int c = (tid & 7) * 8;
        float4 k0 = *(const float4*)(Kg + (size_t)(kt + r) * DH + c);
        float4 k1 = *(const float4*)(Kg + (size_t)(kt + r) * DH + c + 4);
        float4 v0 = *(const float4*)(Vg + (size_t)(kt + r) * DH + c);
        float4 v1 = *(const float4*)(Vg + (size_t)(kt + r) * DH + c + 4);
        float mv  = mask[(size_t)b * SEQ + kt + r];

        __syncthreads();   // prev phase-2 done with Us/Vs
        *(float4*)&Ks[r][c]     = k0;
        *(float4*)&Ks[r][c + 4] = k1;
        *(float4*)&Vs[r][c]     = make_float4(v0.x * mv, v0.y * mv, v0.z * mv, v0.w * mv);
        *(float4*)&Vs[r][c + 4] = make_float4(v1.x * mv, v1.y * mv, v1.z * mv, v1.w * mv);
        __syncthreads();

        // Phase 1: scores, even/odd k packed in the two f32x2 lanes
        u64 s2[2][4];
#pragma unroll
        for (int i = 0; i < 2; i++)
#pragma unroll
            for (int j = 0; j < 4; j++) s2[i][j] = 0ULL;

#pragma unroll 8
        for (int kp = 0; kp < 32; kp++) {
            u64 q0 = *(const u64*)&Qs[p1r][2 * kp];
            u64 q1 = *(const u64*)&Qs[p1r + 1][2 * kp];
#pragma unroll
            for (int j = 0; j < 4; j++) {
                u64 kv = *(const u64*)&Ks[p1c + j][2 * kp];
                s2[0][j] = ffma2(q0, kv, s2[0][j]);
                s2[1][j] = ffma2(q1, kv, s2[1][j]);
            }
        }
#pragma unroll
        for (int i = 0; i < 2; i++) {
            float uu[4];
#pragma unroll
            for (int j = 0; j < 4; j++) {
                float2 hv = unpk(s2[i][j]);
                float sc = hv.x + hv.y;
                float t = fmaf(sc, 0.125f, 5.0f);
                uu[j] = t * t;
            }
            *(float2*)&Us[p1r + i][p1c]     = make_float2(uu[0], uu[1]);
            *(float2*)&Us[p1r + i][p1c + 2] = make_float2(uu[2], uu[3]);
        }
        __syncthreads();

        // Phase 2: acc += u * Vmasked ; den += u
#pragma unroll 4
        for (int kk = 0; kk < 32; kk++) {
            float u0 = Us[rp * 2][kk];
            float u1 = Us[rp * 2 + 1][kk];
            u64 ud0 = dup2(u0);
            u64 ud1 = dup2(u1);
            float4 va = *(const float4*)&Vs[kk][dA];
            float4 vb = *(const float4*)&Vs[kk][dB];
            u64 va0 = pk2(va.x, va.y), va1 = pk2(va.z, va.w);
            u64 vb0 = pk2(vb.x, vb.y), vb1 = pk2(vb.z, vb.w);
            accA[0][0] = ffma2(ud0, va0, accA[0][0]);
            accA[0][1] = ffma2(ud0, va1, accA[0][1]);
            accA[1][0] = ffma2(ud1, va0, accA[1][0]);
            accA[1][1] = ffma2(ud1, va1, accA[1][1]);
            accB[0][0] = ffma2(ud0, vb0, accB[0][0]);
            accB[0][1] = ffma2(ud0, vb1, accB[0][1]);
            accB[1][0] = ffma2(ud1, vb0, accB[1][0]);
            accB[1][1] = ffma2(ud1, vb1, accB[1][1]);
            den0 += u0;
            den1 += u1;
        }
    }

    float inv0 = 1.0f / (den0 + 1e-10f);
    float inv1 = 1.0f / (den1 + 1e-10f);

    {
        int row0 = qt + rp * 2;
        float* o0 = out + ((size_t)b * SEQ + row0) * DM + h * DH;
        float* o1 = out + ((size_t)b * SEQ + row0 + 1) * DM + h * DH;
        float2 a00 = unpk(accA[0][0]), a01 = unpk(accA[0][1]);
        float2 a10 = unpk(accA[1][0]), a11 = unpk(accA[1][1]);
        float2 b00 = unpk(accB[0][0]), b01 = unpk(accB[0][1]);
        float2 b10 = unpk(accB[1][0]), b11 = unpk(accB[1][1]);
        *(float4*)(o0 + dA) = make_float4(a00.x * inv0, a00.y * inv0, a01.x * inv0, a01.y * inv0);
        *(float4*)(o0 + dB) = make_float4(b00.x * inv0, b00.y * inv0, b01.x * inv0, b01.y * inv0);
        *(float4*)(o1 + dA) = make_float4(a10.x * inv1, a10.y * inv1, a11.x * inv1, a11.y * inv1);
        *(float4*)(o1 + dB) = make_float4(b10.x * inv1, b10.y * inv1, b11.x * inv1, b11.y * inv1);
    }
}

// ---------------------------------------------------------------------------
extern "C" void kernel_launch(void* const* d_in, const int* in_sizes, int n_in,
                              void* d_out, int out_size)
{
    const float* hidden = (const float*)d_in[0];
    const float* mask   = (const float*)d_in[1];
    const float* Wq     = (const float*)d_in[2];
    const float* bq     = (const float*)d_in[3];
    const float* Wk     = (const float*)d_in[4];
    const float* bk     = (const float*)d_in[5];
    const float* Wv     = (const float*)d_in[6];
    const float* bv     = (const float*)d_in[7];
    float* out = (float*)d_out;

    const int BS = in_sizes[1];        // mask has B*S elements
    const int B  = BS / SEQ;
    const int M  = BS;

    dim3 g1(3 * DM / 64, M / 128);
    qkv_gemm_kernel<<<g1, 256>>>(hidden, Wq, bq, Wk, bk, Wv, bv);

    dim3 g2(SEQ / 64, NH, B);
    attn_kernel<<<g2, 256>>>(mask, out);
}

// round 4
// speedup vs baseline: 1.8366x; 1.8049x over previous
#include <cuda_runtime.h>
#include <cstdint>

#define NH 12
#define DH 64
#define SEQ 512
#define DM 768
#define MAXB 32

typedef unsigned long long u64;

// ============================ PTX helpers ============================
__device__ __forceinline__ float tf32r(float x) {
    float r; asm("cvt.rna.tf32.f32 %0, %1;" : "=f"(r) : "f"(x)); return r;
}
// mma.sync m16n8k8 tf32: D += A*B  (C regs updated in place)
__device__ __forceinline__ void mma8(float* c, const uint32_t* a, const uint32_t* b) {
    asm volatile(
        "mma.sync.aligned.m16n8k8.row.col.f32.tf32.tf32.f32 "
        "{%0,%1,%2,%3}, {%4,%5,%6,%7}, {%8,%9}, {%0,%1,%2,%3};"
        : "+f"(c[0]), "+f"(c[1]), "+f"(c[2]), "+f"(c[3])
        : "r"(a[0]), "r"(a[1]), "r"(a[2]), "r"(a[3]), "r"(b[0]), "r"(b[1]));
}
__device__ __forceinline__ uint32_t fbits(float x) { return __float_as_uint(x); }

// ============================ device scratch ============================
__device__ float g_q[(size_t)MAXB * NH * SEQ * DH];   // tf32-rounded
__device__ float g_k[(size_t)MAXB * NH * SEQ * DH];   // tf32-rounded
__device__ float g_v[(size_t)MAXB * NH * SEQ * DH];   // fp32
__device__ float g_ah[(size_t)MAXB * SEQ * DM];       // hidden hi (tf32)
__device__ float g_al[(size_t)MAXB * SEQ * DM];       // hidden lo (tf32)
__device__ float g_wth[(size_t)3 * DM * DM];          // W^T [mat][n][k] hi
__device__ float g_wtl[(size_t)3 * DM * DM];          // lo

// ---------------------------------------------------------------------------
// hidden split: x -> (hi, lo) tf32 pair
// ---------------------------------------------------------------------------
__global__ void hsplit_kernel(const float* __restrict__ h, int n4) {
    int i = blockIdx.x * blockDim.x + threadIdx.x;
    if (i >= n4) return;
    float4 x = ((const float4*)h)[i];
    float4 hi, lo;
    hi.x = tf32r(x.x); lo.x = tf32r(x.x - hi.x);
    hi.y = tf32r(x.y); lo.y = tf32r(x.y - hi.y);
    hi.z = tf32r(x.z); lo.z = tf32r(x.z - hi.z);
    hi.w = tf32r(x.w); lo.w = tf32r(x.w - hi.w);
    ((float4*)g_ah)[i] = hi;
    ((float4*)g_al)[i] = lo;
}

// ---------------------------------------------------------------------------
// W transpose + split: Wt[mat][n][k] = split(W[mat][k][n])
// ---------------------------------------------------------------------------
__global__ void wsplit_kernel(const float* __restrict__ Wq,
                              const float* __restrict__ Wk,
                              const float* __restrict__ Wv) {
    __shared__ float th[32][33];
    __shared__ float tl[32][33];
    int mat = blockIdx.z;
    const float* W = (mat == 0) ? Wq : ((mat == 1) ? Wk : Wv);
    int k0 = blockIdx.y * 32, n0 = blockIdx.x * 32;
    int tx = threadIdx.x, ty = threadIdx.y;   // 32 x 8
#pragma unroll
    for (int j = 0; j < 32; j += 8) {
        float x = W[(size_t)(k0 + ty + j) * DM + n0 + tx];
        float hi = tf32r(x);
        th[ty + j][tx] = hi;
        tl[ty + j][tx] = tf32r(x - hi);
    }
    __syncthreads();
    float* oh = g_wth + (size_t)mat * DM * DM;
    float* ol = g_wtl + (size_t)mat * DM * DM;
#pragma unroll
    for (int j = 0; j < 32; j += 8) {
        oh[(size_t)(n0 + ty + j) * DM + k0 + tx] = th[tx][ty + j];
        ol[(size_t)(n0 + ty + j) * DM + k0 + tx] = tl[tx][ty + j];
    }
}

// ---------------------------------------------------------------------------
// QKV GEMM via mma.sync tf32, 2-term split (hh + hl + lh).
// CTA 128(m) x 128(n); 8 warps as 2(m) x 4(n); warp 64x32 = 4x4 m16n8 tiles.
// K-chunks of 32 (4 ksteps). Epilogue: +bias; tf32-round for Q,K; scatter.
// Smem stride 36 -> all fragment LDS patterns conflict-free.
// ---------------------------------------------------------------------------
#define GEMM_SMEM (4 * 128 * 36 * 4)

__global__ __launch_bounds__(256) void qkv_mma_kernel(
    const float* __restrict__ bq, const float* __restrict__ bk,
    const float* __restrict__ bv)
{
    extern __shared__ float sm[];
    float* Ah = sm;                  // [128][36]
    float* Al = Ah + 128 * 36;
    float* Bh = Al + 128 * 36;       // [128 n][36]
    float* Bl = Bh + 128 * 36;

    const int tid  = threadIdx.x;
    const int lane = tid & 31;
    const int wid  = tid >> 5;
    const int wm   = wid >> 2;       // 0..1
    const int wn   = wid & 3;        // 0..3
    const int lr   = lane >> 2;      // 0..7
    const int lc   = lane & 3;       // 0..3

    const int m0  = blockIdx.x * 128;
    const int gn  = blockIdx.y * 128;
    const int mat = gn / DM;
    const int n0  = gn - mat * DM;

    const float* Wh = g_wth + (size_t)mat * DM * DM + (size_t)n0 * DM;
    const float* Wl = g_wtl + (size_t)mat * DM * DM + (size_t)n0 * DM;

    float c[4][4][4];
#pragma unroll
    for (int i = 0; i < 4; i++)
#pragma unroll
        for (int j = 0; j < 4; j++)
#pragma unroll
            for (int q = 0; q < 4; q++) c[i][j][q] = 0.0f;

    const int lrow = tid >> 1;           // 0..127
    const int lseg = (tid & 1) * 16;     // 0 or 16

    for (int k0 = 0; k0 < DM; k0 += 32) {
        __syncthreads();
        {
            const float* pah = g_ah + (size_t)(m0 + lrow) * DM + k0 + lseg;
            const float* pal = g_al + (size_t)(m0 + lrow) * DM + k0 + lseg;
            const float* pbh = Wh + (size_t)lrow * DM + k0 + lseg;
            const float* pbl = Wl + (size_t)lrow * DM + k0 + lseg;
            float* sah = &Ah[lrow * 36 + lseg];
            float* sal = &Al[lrow * 36 + lseg];
            float* sbh = &Bh[lrow * 36 + lseg];
            float* sbl = &Bl[lrow * 36 + lseg];
#pragma unroll
            for (int i = 0; i < 4; i++) {
                *(float4*)(sah + i * 4) = *(const float4*)(pah + i * 4);
                *(float4*)(sal + i * 4) = *(const float4*)(pal + i * 4);
                *(float4*)(sbh + i * 4) = *(const float4*)(pbh + i * 4);
                *(float4*)(sbl + i * 4) = *(const float4*)(pbl + i * 4);
            }
        }
        __syncthreads();

#pragma unroll
        for (int ks = 0; ks < 4; ks++) {
            const int kc = ks * 8;
            uint32_t ah[4][4], al[4][4];
#pragma unroll
            for (int mt = 0; mt < 4; mt++) {
                const int rb = wm * 64 + mt * 16;
                ah[mt][0] = fbits(Ah[(rb + lr) * 36 + kc + lc]);
                ah[mt][1] = fbits(Ah[(rb + lr + 8) * 36 + kc + lc]);
                ah[mt][2] = fbits(Ah[(rb + lr) * 36 + kc + 4 + lc]);
                ah[mt][3] = fbits(Ah[(rb + lr + 8) * 36 + kc + 4 + lc]);
                al[mt][0] = fbits(Al[(rb + lr) * 36 + kc + lc]);
                al[mt][1] = fbits(Al[(rb + lr + 8) * 36 + kc + lc]);
                al[mt][2] = fbits(Al[(rb + lr) * 36 + kc + 4 + lc]);
                al[mt][3] = fbits(Al[(rb + lr + 8) * 36 + kc + 4 + lc]);
            }
            uint32_t bh[4][2], bl[4][2];
#pragma unroll
            for (int nt = 0; nt < 4; nt++) {
                const int nb = wn * 32 + nt * 8;
                bh[nt][0] = fbits(Bh[(nb + lr) * 36 + kc + lc]);
                bh[nt][1] = fbits(Bh[(nb + lr) * 36 + kc + 4 + lc]);
                bl[nt][0] = fbits(Bl[(nb + lr) * 36 + kc + lc]);
                bl[nt][1] = fbits(Bl[(nb + lr) * 36 + kc + 4 + lc]);
            }
#pragma unroll
            for (int mt = 0; mt < 4; mt++)
#pragma unroll
                for (int nt = 0; nt < 4; nt++) {
                    mma8(c[mt][nt], ah[mt], bh[nt]);
                    mma8(c[mt][nt], ah[mt], bl[nt]);
                    mma8(c[mt][nt], al[mt], bh[nt]);
                }
        }
    }

    // epilogue
    const float* bias = (mat == 0) ? bq : ((mat == 1) ? bk : bv);
    float* dst        = (mat == 0) ? g_q : ((mat == 1) ? g_k : g_v);
    const bool rqk    = (mat != 2);
#pragma unroll
    for (int mt = 0; mt < 4; mt++) {
        const int m = m0 + wm * 64 + mt * 16 + lr;
#pragma unroll
        for (int nt = 0; nt < 4; nt++) {
            const int n = n0 + wn * 32 + nt * 8 + 2 * lc;
            const int hh = n >> 6, d = n & 63;
            const float b0 = bias[n], b1 = bias[n + 1];
#pragma unroll
            for (int half = 0; half < 2; half++) {
                const int mm = m + half * 8;
                const int bi = mm >> 9, srow = mm & 511;
                float v0 = c[mt][nt][half * 2 + 0] + b0;
                float v1 = c[mt][nt][half * 2 + 1] + b1;
                if (rqk) { v0 = tf32r(v0); v1 = tf32r(v1); }
                float* o = dst + (((size_t)(bi * NH + hh)) * SEQ + srow) * DH + d;
                *(float2*)o = make_float2(v0, v1);
            }
        }
    }
}

// ---------------------------------------------------------------------------
// Power-law attention via mma.sync tf32.
// Block: 128 q-rows for one (b,h). kt tiles of 64 keys.
// Phase1: S = Q K^T -> u = (S/8+5)^2 (tf32-rounded) -> Us smem.
// Phase2: O += U * (mask*V); den from the same U A-fragments (quad-reduced).
// Warps: phase1 4(m) x 2(keys); phase2 4(m) x 2(d).
// ---------------------------------------------------------------------------
#define ATTN_SMEM ((128 * 68 + 64 * 68 + 64 * 72 + 128 * 68) * 4)

__global__ __launch_bounds__(256) void attn_kernel(
    const float* __restrict__ mask, float* __restrict__ out)
{
    extern __shared__ float sm[];
    float* Qs = sm;                      // [128][68]
    float* Ks = Qs + 128 * 68;           // [64][68]
    float* Vs = Ks + 64 * 68;            // [64][72]
    float* Us = Vs + 64 * 72;            // [128][68]

    const int b  = blockIdx.z;
    const int h  = blockIdx.y;
    const int qt = blockIdx.x * 128;

    const float* Qg = g_q + (((size_t)(b * NH + h)) * SEQ + qt) * DH;
    const float* Kg = g_k + ((size_t)(b * NH + h)) * SEQ * DH;
    const float* Vg = g_v + ((size_t)(b * NH + h)) * SEQ * DH;

    const int tid  = threadIdx.x;
    const int lane = tid & 31;
    const int wid  = tid >> 5;
    const int wm   = wid >> 1;       // 0..3  (32 q-rows)
    const int wn   = wid & 1;        // 0..1  (32 keys / 32 dims)
    const int lr   = lane >> 2;
    const int lc   = lane & 3;

    // load Q tile (128 x 64)
    {
        const int r = tid >> 1;
        const int sgm = (tid & 1) * 32;
        const float* src = Qg + (size_t)r * DH + sgm;
        float* dstq = &Qs[r * 68 + sgm];
#pragma unroll
        for (int i = 0; i < 8; i++)
            *(float4*)(dstq + i * 4) = *(const float4*)(src + i * 4);
    }

    float o[2][4][4];
#pragma unroll
    for (int i = 0; i < 2; i++)
#pragma unroll
        for (int j = 0; j < 4; j++)
#pragma unroll
            for (int q = 0; q < 4; q++) o[i][j][q] = 0.0f;
    float den[2][2] = {{0.0f, 0.0f}, {0.0f, 0.0f}};

    for (int kt = 0; kt < SEQ; kt += 64) {
        __syncthreads();   // prev phase2 done with Us/Vs; Q visible after 1st
        // load K, V (64 x 64); V: mask premult + tf32 round
        {
            const int r = tid >> 2;
            const int sgm = (tid & 3) * 16;
            const float mv = mask[(size_t)b * SEQ + kt + r];
            const float* ksrc = Kg + (size_t)(kt + r) * DH + sgm;
            const float* vsrc = Vg + (size_t)(kt + r) * DH + sgm;
            float* kd = &Ks[r * 68 + sgm];
            float* vd = &Vs[r * 72 + sgm];
#pragma unroll
            for (int i = 0; i < 4; i++) {
                *(float4*)(kd + i * 4) = *(const float4*)(ksrc + i * 4);
                float4 vv = *(const float4*)(vsrc + i * 4);
                vd[i * 4 + 0] = tf32r(vv.x * mv);
                vd[i * 4 + 1] = tf32r(vv.y * mv);
                vd[i * 4 + 2] = tf32r(vv.z * mv);
                vd[i * 4 + 3] = tf32r(vv.w * mv);
            }
        }
        __syncthreads();

        // ---- phase 1: S = Q K^T over d=64 (8 ksteps) ----
        float s[2][4][4];
#pragma unroll
        for (int i = 0; i < 2; i++)
#pragma unroll
            for (int j = 0; j < 4; j++)
#pragma unroll
                for (int q = 0; q < 4; q++) s[i][j][q] = 0.0f;

#pragma unroll
        for (int ks = 0; ks < 8; ks++) {
            const int kc = ks * 8;
            uint32_t a[2][4];
#pragma unroll
            for (int mt = 0; mt < 2; mt++) {
                const int rb = wm * 32 + mt * 16;
                a[mt][0] = fbits(Qs[(rb + lr) * 68 + kc + lc]);
                a[mt][1] = fbits(Qs[(rb + lr + 8) * 68 + kc + lc]);
                a[mt][2] = fbits(Qs[(rb + lr) * 68 + kc + 4 + lc]);
                a[mt][3] = fbits(Qs[(rb + lr + 8) * 68 + kc + 4 + lc]);
            }
            uint32_t bb[4][2];
#pragma unroll
            for (int nt = 0; nt < 4; nt++) {
                const int nb = wn * 32 + nt * 8;
                bb[nt][0] = fbits(Ks[(nb + lr) * 68 + kc + lc]);
                bb[nt][1] = fbits(Ks[(nb + lr) * 68 + kc + 4 + lc]);
            }
#pragma unroll
            for (int mt = 0; mt < 2; mt++)
#pragma unroll
                for (int nt = 0; nt < 4; nt++)
                    mma8(s[mt][nt], a[mt], bb[nt]);
        }
        // transform + store U (tf32-rounded)
#pragma unroll
        for (int mt = 0; mt < 2; mt++) {
            const int rb = wm * 32 + mt * 16;
#pragma unroll
            for (int nt = 0; nt < 4; nt++) {
                const int cb = wn * 32 + nt * 8 + 2 * lc;
                float t0 = fmaf(s[mt][nt][0], 0.125f, 5.0f);
                float t1 = fmaf(s[mt][nt][1], 0.125f, 5.0f);
                float t2 = fmaf(s[mt][nt][2], 0.125f, 5.0f);
                float t3 = fmaf(s[mt][nt][3], 0.125f, 5.0f);
                *(float2*)&Us[(rb + lr) * 68 + cb] =
                    make_float2(tf32r(t0 * t0), tf32r(t1 * t1));
                *(float2*)&Us[(rb + lr + 8) * 68 + cb] =
                    make_float2(tf32r(t2 * t2), tf32r(t3 * t3));
            }
        }
        __syncthreads();

        // ---- phase 2: O += U * V ; den += rowsum(U) ----
#pragma unroll
        for (int ks = 0; ks < 8; ks++) {
            const int kc = ks * 8;
            uint32_t a[2][4];
#pragma unroll
            for (int mt = 0; mt < 2; mt++) {
                const int rb = wm * 32 + mt * 16;
                float f0 = Us[(rb + lr) * 68 + kc + lc];
                float f1 = Us[(rb + lr + 8) * 68 + kc + lc];
                float f2 = Us[(rb + lr) * 68 + kc + 4 + lc];
                float f3 = Us[(rb + lr + 8) * 68 + kc + 4 + lc];
                den[mt][0] += f0 + f2;
                den[mt][1] += f1 + f3;
                a[mt][0] = fbits(f0); a[mt][1] = fbits(f1);
                a[mt][2] = fbits(f2); a[mt][3] = fbits(f3);
            }
            uint32_t bb[4][2];
#pragma unroll
            for (int nt = 0; nt < 4; nt++) {
                const int db = wn * 32 + nt * 8 + lr;
                bb[nt][0] = fbits(Vs[(kc + lc) * 72 + db]);
                bb[nt][1] = fbits(Vs[(kc + 4 + lc) * 72 + db]);
            }
#pragma unroll
            for (int mt = 0; mt < 2; mt++)
#pragma unroll
                for (int nt = 0; nt < 4; nt++)
                    mma8(o[mt][nt], a[mt], bb[nt]);
        }
    }

    // quad-reduce den (lanes within a quad share rows)
#pragma unroll
    for (int mt = 0; mt < 2; mt++)
#pragma unroll
        for (int j = 0; j < 2; j++) {
            float v = den[mt][j];
            v += __shfl_xor_sync(0xFFFFFFFFu, v, 1);
            v += __shfl_xor_sync(0xFFFFFFFFu, v, 2);
            den[mt][j] = v;
        }

#pragma unroll
    for (int mt = 0; mt < 2; mt++) {
        const float inv0 = 1.0f / (den[mt][0] + 1e-10f);
        const float inv1 = 1.0f / (den[mt][1] + 1e-10f);
        const int rb = qt + wm * 32 + mt * 16 + lr;
#pragma unroll
        for (int nt = 0; nt < 4; nt++) {
            const int d = wn * 32 + nt * 8 + 2 * lc;
            float* o0 = out + ((size_t)b * SEQ + rb) * DM + h * DH + d;
            float* o1 = out + ((size_t)b * SEQ + rb + 8) * DM + h * DH + d;
            *(float2*)o0 = make_float2(o[mt][nt][0] * inv0, o[mt][nt][1] * inv0);
            *(float2*)o1 = make_float2(o[mt][nt][2] * inv1, o[mt][nt][3] * inv1);
        }
    }
}

// ---------------------------------------------------------------------------
extern "C" void kernel_launch(void* const* d_in, const int* in_sizes, int n_in,
                              void* d_out, int out_size)
{
    const float* hidden = (const float*)d_in[0];
    const float* mask   = (const float*)d_in[1];
    const float* Wq     = (const float*)d_in[2];
    const float* bq     = (const float*)d_in[3];
    const float* Wk     = (const float*)d_in[4];
    const float* bk     = (const float*)d_in[5];
    const float* Wv     = (const float*)d_in[6];
    const float* bv     = (const float*)d_in[7];
    float* out = (float*)d_out;

    const int BS = in_sizes[1];
    const int B  = BS / SEQ;
    const int M  = BS;

    cudaFuncSetAttribute(qkv_mma_kernel,
                         cudaFuncAttributeMaxDynamicSharedMemorySize, GEMM_SMEM);
    cudaFuncSetAttribute(attn_kernel,
                         cudaFuncAttributeMaxDynamicSharedMemorySize, ATTN_SMEM);

    int n4 = M * DM / 4;
    hsplit_kernel<<<(n4 + 255) / 256, 256>>>(hidden, n4);

    dim3 gw(DM / 32, DM / 32, 3);
    wsplit_kernel<<<gw, dim3(32, 8)>>>(Wq, Wk, Wv);

    dim3 gm(M / 128, 18);
    qkv_mma_kernel<<<gm, 256, GEMM_SMEM>>>(bq, bk, bv);

    dim3 g2(SEQ / 128, NH, B);
    attn_kernel<<<g2, 256, ATTN_SMEM>>>(mask, out);
}

// round 5
// speedup vs baseline: 3.1219x; 1.6999x over previous
#include <cuda_runtime.h>
#include <cstdint>

#define NH 12
#define DH 64
#define SEQ 512
#define DM 768
#define MAXB 32

typedef unsigned long long u64;

// ============================ PTX helpers ============================
__device__ __forceinline__ float tf32r(float x) {
    float r; asm("cvt.rna.tf32.f32 %0, %1;" : "=f"(r) : "f"(x)); return r;
}
__device__ __forceinline__ void mma8(float* c, const uint32_t* a, const uint32_t* b) {
    asm volatile(
        "mma.sync.aligned.m16n8k8.row.col.f32.tf32.tf32.f32 "
        "{%0,%1,%2,%3}, {%4,%5,%6,%7}, {%8,%9}, {%0,%1,%2,%3};"
        : "+f"(c[0]), "+f"(c[1]), "+f"(c[2]), "+f"(c[3])
        : "r"(a[0]), "r"(a[1]), "r"(a[2]), "r"(a[3]), "r"(b[0]), "r"(b[1]));
}
__device__ __forceinline__ uint32_t fbits(float x) { return __float_as_uint(x); }
__device__ __forceinline__ uint32_t smem_u32(const void* p) {
    uint32_t a;
    asm("{ .reg .u64 t; cvta.to.shared.u64 t, %1; cvt.u32.u64 %0, t; }" : "=r"(a) : "l"(p));
    return a;
}
__device__ __forceinline__ void cpa16(uint32_t s, const float* g) {
    asm volatile("cp.async.cg.shared.global [%0], [%1], 16;" :: "r"(s), "l"(g));
}
__device__ __forceinline__ void cpa_commit() {
    asm volatile("cp.async.commit_group;" ::: "memory");
}
template<int N>
__device__ __forceinline__ void cpa_wait() {
    asm volatile("cp.async.wait_group %0;" :: "n"(N) : "memory");
}

// ============================ device scratch ============================
__device__ float g_q[(size_t)MAXB * NH * SEQ * DH];   // tf32-rounded
__device__ float g_k[(size_t)MAXB * NH * SEQ * DH];   // tf32-rounded
__device__ float g_v[(size_t)MAXB * NH * SEQ * DH];   // fp32
__device__ float g_ah[(size_t)MAXB * SEQ * DM];       // hidden hi (tf32)
__device__ float g_al[(size_t)MAXB * SEQ * DM];       // hidden lo (tf32)
__device__ float g_wth[(size_t)3 * DM * DM];          // W^T [mat][n][k] hi
__device__ float g_wtl[(size_t)3 * DM * DM];          // lo (unused now, kept)

// ---------------------------------------------------------------------------
__global__ void hsplit_kernel(const float* __restrict__ h, int n4) {
    int i = blockIdx.x * blockDim.x + threadIdx.x;
    if (i >= n4) return;
    float4 x = ((const float4*)h)[i];
    float4 hi, lo;
    hi.x = tf32r(x.x); lo.x = tf32r(x.x - hi.x);
    hi.y = tf32r(x.y); lo.y = tf32r(x.y - hi.y);
    hi.z = tf32r(x.z); lo.z = tf32r(x.z - hi.z);
    hi.w = tf32r(x.w); lo.w = tf32r(x.w - hi.w);
    ((float4*)g_ah)[i] = hi;
    ((float4*)g_al)[i] = lo;
}

// ---------------------------------------------------------------------------
// W transpose (hi only needed now): Wt[mat][n][k] = tf32(W[mat][k][n])
// ---------------------------------------------------------------------------
__global__ void wsplit_kernel(const float* __restrict__ Wq,
                              const float* __restrict__ Wk,
                              const float* __restrict__ Wv) {
    __shared__ float th[32][33];
    int mat = blockIdx.z;
    const float* W = (mat == 0) ? Wq : ((mat == 1) ? Wk : Wv);
    int k0 = blockIdx.y * 32, n0 = blockIdx.x * 32;
    int tx = threadIdx.x, ty = threadIdx.y;   // 32 x 8
#pragma unroll
    for (int j = 0; j < 32; j += 8)
        th[ty + j][tx] = tf32r(W[(size_t)(k0 + ty + j) * DM + n0 + tx]);
    __syncthreads();
    float* oh = g_wth + (size_t)mat * DM * DM;
#pragma unroll
    for (int j = 0; j < 32; j += 8)
        oh[(size_t)(n0 + ty + j) * DM + k0 + tx] = th[tx][ty + j];
}

// ---------------------------------------------------------------------------
// Pipelined QKV GEMM via mma.sync tf32 + cp.async.
// TERMS=1 (Q,K): D = A_hi · W_hi           (2 tiles/stage)
// TERMS=2 (V):   D = (A_hi + A_lo) · W_hi  (3 tiles/stage)
// CTA 128x128; 8 warps 2(m)x4(n), warp 64x32; K-chunk 32 (4 ksteps).
// ---------------------------------------------------------------------------
#define TILE_F (128 * 36)
#define TILE_B (TILE_F * 4)

template<int TERMS, int STAGES>
__global__ __launch_bounds__(256) void gemm_tpl(
    const float* __restrict__ bq, const float* __restrict__ bk,
    const float* __restrict__ bv, int mat_base)
{
    constexpr int TILES = (TERMS == 1) ? 2 : 3;
    extern __shared__ float sm[];

    const int tid  = threadIdx.x;
    const int lane = tid & 31;
    const int wid  = tid >> 5;
    const int wm   = wid >> 2;       // 0..1
    const int wn   = wid & 3;        // 0..3
    const int lr   = lane >> 2;      // 0..7
    const int lc   = lane & 3;       // 0..3

    const int m0  = blockIdx.x * 128;
    const int yb  = blockIdx.y;
    const int mat = mat_base + yb / 6;
    const int n0  = (yb % 6) * 128;

    const float* Wh = g_wth + (size_t)mat * DM * DM + (size_t)n0 * DM;

    // per-thread load mapping: half-row each (64B) per tile
    const int lrow = tid >> 1;
    const int lseg = (tid & 1) * 16;
    const float* gA = g_ah + (size_t)(m0 + lrow) * DM + lseg;
    const float* gL = g_al + (size_t)(m0 + lrow) * DM + lseg;
    const float* gB = Wh + (size_t)lrow * DM + lseg;
    const uint32_t sb   = smem_u32(sm);
    const uint32_t soff = (uint32_t)(lrow * 36 + lseg) * 4;

#define ISSUE(ch, st)                                                        \
    do {                                                                     \
        const float* _a = gA + (ch) * 32;                                    \
        const float* _b = gB + (ch) * 32;                                    \
        uint32_t _s0 = sb + ((st) * TILES + 0) * TILE_B + soff;              \
        uint32_t _s1 = sb + ((st) * TILES + 1) * TILE_B + soff;              \
        _Pragma("unroll")                                                    \
        for (int _i = 0; _i < 4; _i++) {                                     \
            cpa16(_s0 + _i * 16, _a + _i * 4);                               \
            cpa16(_s1 + _i * 16, _b + _i * 4);                               \
        }                                                                    \
        if (TERMS == 2) {                                                    \
            const float* _l = gL + (ch) * 32;                                \
            uint32_t _s2 = sb + ((st) * TILES + 2) * TILE_B + soff;          \
            _Pragma("unroll")                                                \
            for (int _i = 0; _i < 4; _i++)                                   \
                cpa16(_s2 + _i * 16, _l + _i * 4);                           \
        }                                                                    \
    } while (0)

    float c[4][4][4];
#pragma unroll
    for (int i = 0; i < 4; i++)
#pragma unroll
        for (int j = 0; j < 4; j++)
#pragma unroll
            for (int q = 0; q < 4; q++) c[i][j][q] = 0.0f;

    const int NCH = DM / 32;   // 24

    // prologue: prefetch chunks 0..STAGES-2
#pragma unroll
    for (int p = 0; p < STAGES - 1; p++) {
        ISSUE(p, p);
        cpa_commit();
    }

    for (int ch = 0; ch < NCH; ch++) {
        const int pre = ch + STAGES - 1;
        if (pre < NCH) ISSUE(pre, pre % STAGES);
        cpa_commit();
        cpa_wait<STAGES - 1>();
        __syncthreads();

        const int st = ch % STAGES;
        const float* Ah = sm + (st * TILES + 0) * TILE_F;
        const float* Bh = sm + (st * TILES + 1) * TILE_F;
        const float* Al = sm + (st * TILES + 2) * TILE_F;   // valid iff TERMS==2

#pragma unroll
        for (int ks = 0; ks < 4; ks++) {
            const int kc = ks * 8;
            uint32_t ah[4][4];
#pragma unroll
            for (int mt = 0; mt < 4; mt++) {
                const int rb = wm * 64 + mt * 16;
                ah[mt][0] = fbits(Ah[(rb + lr) * 36 + kc + lc]);
                ah[mt][1] = fbits(Ah[(rb + lr + 8) * 36 + kc + lc]);
                ah[mt][2] = fbits(Ah[(rb + lr) * 36 + kc + 4 + lc]);
                ah[mt][3] = fbits(Ah[(rb + lr + 8) * 36 + kc + 4 + lc]);
            }
            uint32_t bh[4][2];
#pragma unroll
            for (int nt = 0; nt < 4; nt++) {
                const int nb = wn * 32 + nt * 8;
                bh[nt][0] = fbits(Bh[(nb + lr) * 36 + kc + lc]);
                bh[nt][1] = fbits(Bh[(nb + lr) * 36 + kc + 4 + lc]);
            }
#pragma unroll
            for (int mt = 0; mt < 4; mt++)
#pragma unroll
                for (int nt = 0; nt < 4; nt++)
                    mma8(c[mt][nt], ah[mt], bh[nt]);

            if (TERMS == 2) {
                uint32_t al[4][4];
#pragma unroll
                for (int mt = 0; mt < 4; mt++) {
                    const int rb = wm * 64 + mt * 16;
                    al[mt][0] = fbits(Al[(rb + lr) * 36 + kc + lc]);
                    al[mt][1] = fbits(Al[(rb + lr + 8) * 36 + kc + lc]);
                    al[mt][2] = fbits(Al[(rb + lr) * 36 + kc + 4 + lc]);
                    al[mt][3] = fbits(Al[(rb + lr + 8) * 36 + kc + 4 + lc]);
                }
#pragma unroll
                for (int mt = 0; mt < 4; mt++)
#pragma unroll
                    for (int nt = 0; nt < 4; nt++)
                        mma8(c[mt][nt], al[mt], bh[nt]);
            }
        }
        __syncthreads();
    }
#undef ISSUE

    // epilogue
    const float* bias = (mat == 0) ? bq : ((mat == 1) ? bk : bv);
    float* dst        = (mat == 0) ? g_q : ((mat == 1) ? g_k : g_v);
    const bool rqk    = (TERMS == 1);
#pragma unroll
    for (int mt = 0; mt < 4; mt++) {
        const int m = m0 + wm * 64 + mt * 16 + lr;
#pragma unroll
        for (int nt = 0; nt < 4; nt++) {
            const int n = n0 + wn * 32 + nt * 8 + 2 * lc;
            const int hh = n >> 6, d = n & 63;
            const float b0 = bias[n], b1 = bias[n + 1];
#pragma unroll
            for (int half = 0; half < 2; half++) {
                const int mm = m + half * 8;
                const int bi = mm >> 9, srow = mm & 511;
                float v0 = c[mt][nt][half * 2 + 0] + b0;
                float v1 = c[mt][nt][half * 2 + 1] + b1;
                if (rqk) { v0 = tf32r(v0); v1 = tf32r(v1); }
                float* o = dst + (((size_t)(bi * NH + hh)) * SEQ + srow) * DH + d;
                *(float2*)o = make_float2(v0, v1);
            }
        }
    }
}

// ---------------------------------------------------------------------------
// Power-law attention via mma.sync tf32 (unchanged from R4).
// ---------------------------------------------------------------------------
#define ATTN_SMEM ((128 * 68 + 64 * 68 + 64 * 72 + 128 * 68) * 4)

__global__ __launch_bounds__(256) void attn_kernel(
    const float* __restrict__ mask, float* __restrict__ out)
{
    extern __shared__ float sm[];
    float* Qs = sm;
    float* Ks = Qs + 128 * 68;
    float* Vs = Ks + 64 * 68;
    float* Us = Vs + 64 * 72;

    const int b  = blockIdx.z;
    const int h  = blockIdx.y;
    const int qt = blockIdx.x * 128;

    const float* Qg = g_q + (((size_t)(b * NH + h)) * SEQ + qt) * DH;
    const float* Kg = g_k + ((size_t)(b * NH + h)) * SEQ * DH;
    const float* Vg = g_v + ((size_t)(b * NH + h)) * SEQ * DH;

    const int tid  = threadIdx.x;
    const int lane = tid & 31;
    const int wid  = tid >> 5;
    const int wm   = wid >> 1;
    const int wn   = wid & 1;
    const int lr   = lane >> 2;
    const int lc   = lane & 3;

    {
        const int r = tid >> 1;
        const int sgm = (tid & 1) * 32;
        const float* src = Qg + (size_t)r * DH + sgm;
        float* dstq = &Qs[r * 68 + sgm];
#pragma unroll
        for (int i = 0; i < 8; i++)
            *(float4*)(dstq + i * 4) = *(const float4*)(src + i * 4);
    }

    float o[2][4][4];
#pragma unroll
    for (int i = 0; i < 2; i++)
#pragma unroll
        for (int j = 0; j < 4; j++)
#pragma unroll
            for (int q = 0; q < 4; q++) o[i][j][q] = 0.0f;
    float den[2][2] = {{0.0f, 0.0f}, {0.0f, 0.0f}};

    for (int kt = 0; kt < SEQ; kt += 64) {
        __syncthreads();
        {
            const int r = tid >> 2;
            const int sgm = (tid & 3) * 16;
            const float mv = mask[(size_t)b * SEQ + kt + r];
            const float* ksrc = Kg + (size_t)(kt + r) * DH + sgm;
            const float* vsrc = Vg + (size_t)(kt + r) * DH + sgm;
            float* kd = &Ks[r * 68 + sgm];
            float* vd = &Vs[r * 72 + sgm];
#pragma unroll
            for (int i = 0; i < 4; i++) {
                *(float4*)(kd + i * 4) = *(const float4*)(ksrc + i * 4);
                float4 vv = *(const float4*)(vsrc + i * 4);
                vd[i * 4 + 0] = tf32r(vv.x * mv);
                vd[i * 4 + 1] = tf32r(vv.y * mv);
                vd[i * 4 + 2] = tf32r(vv.z * mv);
                vd[i * 4 + 3] = tf32r(vv.w * mv);
            }
        }
        __syncthreads();

        float s[2][4][4];
#pragma unroll
        for (int i = 0; i < 2; i++)
#pragma unroll
            for (int j = 0; j < 4; j++)
#pragma unroll
                for (int q = 0; q < 4; q++) s[i][j][q] = 0.0f;

#pragma unroll
        for (int ks = 0; ks < 8; ks++) {
            const int kc = ks * 8;
            uint32_t a[2][4];
#pragma unroll
            for (int mt = 0; mt < 2; mt++) {
                const int rb = wm * 32 + mt * 16;
                a[mt][0] = fbits(Qs[(rb + lr) * 68 + kc + lc]);
                a[mt][1] = fbits(Qs[(rb + lr + 8) * 68 + kc + lc]);
                a[mt][2] = fbits(Qs[(rb + lr) * 68 + kc + 4 + lc]);
                a[mt][3] = fbits(Qs[(rb + lr + 8) * 68 + kc + 4 + lc]);
            }
            uint32_t bb[4][2];
#pragma unroll
            for (int nt = 0; nt < 4; nt++) {
                const int nb = wn * 32 + nt * 8;
                bb[nt][0] = fbits(Ks[(nb + lr) * 68 + kc + lc]);
                bb[nt][1] = fbits(Ks[(nb + lr) * 68 + kc + 4 + lc]);
            }
#pragma unroll
            for (int mt = 0; mt < 2; mt++)
#pragma unroll
                for (int nt = 0; nt < 4; nt++)
                    mma8(s[mt][nt], a[mt], bb[nt]);
        }
#pragma unroll
        for (int mt = 0; mt < 2; mt++) {
            const int rb = wm * 32 + mt * 16;
#pragma unroll
            for (int nt = 0; nt < 4; nt++) {
                const int cb = wn * 32 + nt * 8 + 2 * lc;
                float t0 = fmaf(s[mt][nt][0], 0.125f, 5.0f);
                float t1 = fmaf(s[mt][nt][1], 0.125f, 5.0f);
                float t2 = fmaf(s[mt][nt][2], 0.125f, 5.0f);
                float t3 = fmaf(s[mt][nt][3], 0.125f, 5.0f);
                *(float2*)&Us[(rb + lr) * 68 + cb] =
                    make_float2(tf32r(t0 * t0), tf32r(t1 * t1));
                *(float2*)&Us[(rb + lr + 8) * 68 + cb] =
                    make_float2(tf32r(t2 * t2), tf32r(t3 * t3));
            }
        }
        __syncthreads();

#pragma unroll
        for (int ks = 0; ks < 8; ks++) {
            const int kc = ks * 8;
            uint32_t a[2][4];
#pragma unroll
            for (int mt = 0; mt < 2; mt++) {
                const int rb = wm * 32 + mt * 16;
                float f0 = Us[(rb + lr) * 68 + kc + lc];
                float f1 = Us[(rb + lr + 8) * 68 + kc + lc];
                float f2 = Us[(rb + lr) * 68 + kc + 4 + lc];
                float f3 = Us[(rb + lr + 8) * 68 + kc + 4 + lc];
                den[mt][0] += f0 + f2;
                den[mt][1] += f1 + f3;
                a[mt][0] = fbits(f0); a[mt][1] = fbits(f1);
                a[mt][2] = fbits(f2); a[mt][3] = fbits(f3);
            }
            uint32_t bb[4][2];
#pragma unroll
            for (int nt = 0; nt < 4; nt++) {
                const int db = wn * 32 + nt * 8 + lr;
                bb[nt][0] = fbits(Vs[(kc + lc) * 72 + db]);
                bb[nt][1] = fbits(Vs[(kc + 4 + lc) * 72 + db]);
            }
#pragma unroll
            for (int mt = 0; mt < 2; mt++)
#pragma unroll
                for (int nt = 0; nt < 4; nt++)
                    mma8(o[mt][nt], a[mt], bb[nt]);
        }
    }

#pragma unroll
    for (int mt = 0; mt < 2; mt++)
#pragma unroll
        for (int j = 0; j < 2; j++) {
            float v = den[mt][j];
            v += __shfl_xor_sync(0xFFFFFFFFu, v, 1);
            v += __shfl_xor_sync(0xFFFFFFFFu, v, 2);
            den[mt][j] = v;
        }

#pragma unroll
    for (int mt = 0; mt < 2; mt++) {
        const float inv0 = 1.0f / (den[mt][0] + 1e-10f);
        const float inv1 = 1.0f / (den[mt][1] + 1e-10f);
        const int rb = qt + wm * 32 + mt * 16 + lr;
#pragma unroll
        for (int nt = 0; nt < 4; nt++) {
            const int d = wn * 32 + nt * 8 + 2 * lc;
            float* o0 = out + ((size_t)b * SEQ + rb) * DM + h * DH + d;
            float* o1 = out + ((size_t)b * SEQ + rb + 8) * DM + h * DH + d;
            *(float2*)o0 = make_float2(o[mt][nt][0] * inv0, o[mt][nt][1] * inv0);
            *(float2*)o1 = make_float2(o[mt][nt][2] * inv1, o[mt][nt][3] * inv1);
        }
    }
}

// ---------------------------------------------------------------------------
extern "C" void kernel_launch(void* const* d_in, const int* in_sizes, int n_in,
                              void* d_out, int out_size)
{
    const float* hidden = (const float*)d_in[0];
    const float* mask   = (const float*)d_in[1];
    const float* Wq     = (const float*)d_in[2];
    const float* bq     = (const float*)d_in[3];
    const float* Wk     = (const float*)d_in[4];
    const float* bk     = (const float*)d_in[5];
    const float* Wv     = (const float*)d_in[6];
    const float* bv     = (const float*)d_in[7];
    float* out = (float*)d_out;

    const int BS = in_sizes[1];
    const int B  = BS / SEQ;
    const int M  = BS;

    const int smem_qk = 3 * 2 * TILE_B;   // 110592
    const int smem_v  = 2 * 3 * TILE_B;   // 110592

    cudaFuncSetAttribute(gemm_tpl<1, 3>,
                         cudaFuncAttributeMaxDynamicSharedMemorySize, smem_qk);
    cudaFuncSetAttribute(gemm_tpl<2, 2>,
                         cudaFuncAttributeMaxDynamicSharedMemorySize, smem_v);
    cudaFuncSetAttribute(attn_kernel,
                         cudaFuncAttributeMaxDynamicSharedMemorySize, ATTN_SMEM);

    int n4 = M * DM / 4;
    hsplit_kernel<<<(n4 + 255) / 256, 256>>>(hidden, n4);

    dim3 gw(DM / 32, DM / 32, 3);
    wsplit_kernel<<<gw, dim3(32, 8)>>>(Wq, Wk, Wv);

    dim3 gqk(M / 128, 12);   // mats 0 (Q), 1 (K)
    gemm_tpl<1, 3><<<gqk, 256, smem_qk>>>(bq, bk, bv, 0);

    dim3 gv(M / 128, 6);     // mat 2 (V)
    gemm_tpl<2, 2><<<gv, 256, smem_v>>>(bq, bk, bv, 2);

    dim3 g2(SEQ / 128, NH, B);
    attn_kernel<<<g2, 256, ATTN_SMEM>>>(mask, out);
}

// round 6
// speedup vs baseline: 3.7490x; 1.2008x over previous
#include <cuda_runtime.h>
#include <cstdint>

#define NH 12
#define DH 64
#define SEQ 512
#define DM 768
#define MAXB 32

typedef unsigned long long u64;

// ============================ PTX helpers ============================
__device__ __forceinline__ float tf32r(float x) {
    float r; asm("cvt.rna.tf32.f32 %0, %1;" : "=f"(r) : "f"(x)); return r;
}
__device__ __forceinline__ void mma8(float* c, const uint32_t* a, const uint32_t* b) {
    asm volatile(
        "mma.sync.aligned.m16n8k8.row.col.f32.tf32.tf32.f32 "
        "{%0,%1,%2,%3}, {%4,%5,%6,%7}, {%8,%9}, {%0,%1,%2,%3};"
        : "+f"(c[0]), "+f"(c[1]), "+f"(c[2]), "+f"(c[3])
        : "r"(a[0]), "r"(a[1]), "r"(a[2]), "r"(a[3]), "r"(b[0]), "r"(b[1]));
}
__device__ __forceinline__ uint32_t fbits(float x) { return __float_as_uint(x); }
__device__ __forceinline__ uint32_t smem_u32(const void* p) {
    uint32_t a;
    asm("{ .reg .u64 t; cvta.to.shared.u64 t, %1; cvt.u32.u64 %0, t; }" : "=r"(a) : "l"(p));
    return a;
}
__device__ __forceinline__ void cpa16(uint32_t s, const float* g) {
    asm volatile("cp.async.cg.shared.global [%0], [%1], 16;" :: "r"(s), "l"(g));
}
__device__ __forceinline__ void cpa_commit() {
    asm volatile("cp.async.commit_group;" ::: "memory");
}
template<int N>
__device__ __forceinline__ void cpa_wait() {
    asm volatile("cp.async.wait_group %0;" :: "n"(N) : "memory");
}

// ============================ device scratch ============================
__device__ float g_q[(size_t)MAXB * NH * SEQ * DH];     // tf32-rounded
__device__ float g_k[(size_t)MAXB * NH * SEQ * DH];     // tf32-rounded
__device__ float g_v[(size_t)MAXB * NH * SEQ * DH];     // fp32
__device__ float g_aht[(size_t)DM * MAXB * SEQ];        // hidden^T [k][m_perm], tf32
__device__ float g_wth[(size_t)3 * DM * DM];            // W^T [mat][n][k], tf32

// ---------------------------------------------------------------------------
// hidden transpose: g_aht[k][mperm(m)] = tf32(hidden[m][k])
// m-perm within 16-groups: m' = 2*(m%8) + ((m>>3)&1)  (rows r, r+8 adjacent)
// ---------------------------------------------------------------------------
__global__ void htrans_kernel(const float* __restrict__ h, int M) {
    __shared__ float t[32][33];
    const int m0 = blockIdx.x * 32, k0 = blockIdx.y * 32;
    const int tx = threadIdx.x, ty = threadIdx.y;   // 32 x 8
#pragma unroll
    for (int j = 0; j < 32; j += 8)
        t[ty + j][tx] = tf32r(h[(size_t)(m0 + ty + j) * DM + k0 + tx]);
    __syncthreads();
    const int m = m0 + tx;
    const int mp = (m & ~15) | (((m & 7) << 1) | ((m >> 3) & 1));
#pragma unroll
    for (int j = 0; j < 32; j += 8)
        g_aht[(size_t)(k0 + ty + j) * M + mp] = t[tx][ty + j];
}

// ---------------------------------------------------------------------------
// W transpose: g_wth[mat][n][k] = tf32(W[mat][k][n])
// ---------------------------------------------------------------------------
__global__ void wsplit_kernel(const float* __restrict__ Wq,
                              const float* __restrict__ Wk,
                              const float* __restrict__ Wv) {
    __shared__ float th[32][33];
    int mat = blockIdx.z;
    const float* W = (mat == 0) ? Wq : ((mat == 1) ? Wk : Wv);
    int k0 = blockIdx.y * 32, n0 = blockIdx.x * 32;
    int tx = threadIdx.x, ty = threadIdx.y;
#pragma unroll
    for (int j = 0; j < 32; j += 8)
        th[ty + j][tx] = tf32r(W[(size_t)(k0 + ty + j) * DM + n0 + tx]);
    __syncthreads();
    float* oh = g_wth + (size_t)mat * DM * DM;
#pragma unroll
    for (int j = 0; j < 32; j += 8)
        oh[(size_t)(n0 + ty + j) * DM + k0 + tx] = th[tx][ty + j];
}

// ---------------------------------------------------------------------------
// Unified QKV GEMM, single-term tf32, mma.sync + cp.async 3-stage pipeline.
// A: k-major swizzled smem (LDS.64 fragments). B: [n][k] pad-36 (LDS.32).
// CTA 128x128; 8 warps 2(m)x4(n); warp 64x32; K-chunk 32 (4 ksteps).
// ---------------------------------------------------------------------------
#define ASTAGE_F 4096            // 32 k-rows * 128 floats
#define BSTAGE_F (128 * 36)
#define NSTG 3
#define GEMM_SMEM ((NSTG * (ASTAGE_F + BSTAGE_F)) * 4)   // 104448 B

__global__ __launch_bounds__(256) void qkv_gemm_kernel(
    const float* __restrict__ bq, const float* __restrict__ bk,
    const float* __restrict__ bv, int M)
{
    extern __shared__ float sm[];
    float* Bbase = sm + NSTG * ASTAGE_F;

    const int tid  = threadIdx.x;
    const int lane = tid & 31;
    const int wid  = tid >> 5;
    const int wm   = wid >> 2;
    const int wn   = wid & 3;
    const int lr   = lane >> 2;
    const int lc   = lane & 3;

    const int m0  = blockIdx.x * 128;
    const int yb  = blockIdx.y;
    const int mat = yb / 6;
    const int n0  = (yb % 6) * 128;

    const float* Wh = g_wth + (size_t)mat * DM * DM + (size_t)n0 * DM;

    // A load mapping: k-row tid>>3, m-seg (tid&7)*16
    const int ak   = tid >> 3;
    const int ams  = (tid & 7) * 16;
    const float* gA = g_aht + (size_t)ak * M + m0 + ams;
    // B load mapping: n-row tid>>1, k-seg (tid&1)*16
    const int brow = tid >> 1;
    const int bseg = (tid & 1) * 16;
    const float* gB = Wh + (size_t)brow * DM + bseg;

    const uint32_t sbA = smem_u32(sm);
    const uint32_t sbB = smem_u32(Bbase);
    const uint32_t aXor = (uint32_t)((ak & 3) << 1);
    const uint32_t aRow = (uint32_t)ak * 512;            // bytes per k-row
    const uint32_t bOff = (uint32_t)(brow * 36 + bseg) * 4;

#define ISSUE(ch, st)                                                         \
    do {                                                                      \
        const float* _a = gA + (size_t)(ch) * 32 * M;                         \
        const float* _b = gB + (ch) * 32;                                     \
        uint32_t _sa = sbA + (st) * (ASTAGE_F * 4) + aRow;                    \
        uint32_t _sb = sbB + (st) * (BSTAGE_F * 4) + bOff;                    \
        _Pragma("unroll")                                                     \
        for (int _i = 0; _i < 4; _i++) {                                      \
            uint32_t _blk = (uint32_t)((ams >> 2) + _i) ^ aXor;               \
            cpa16(_sa + _blk * 16, _a + _i * 4);                              \
            cpa16(_sb + _i * 16, _b + _i * 4);                                \
        }                                                                     \
    } while (0)

    float c[4][4][4];
#pragma unroll
    for (int i = 0; i < 4; i++)
#pragma unroll
        for (int j = 0; j < 4; j++)
#pragma unroll
            for (int q = 0; q < 4; q++) c[i][j][q] = 0.0f;

    const int NCH = DM / 32;   // 24

#pragma unroll
    for (int p = 0; p < NSTG - 1; p++) {
        ISSUE(p, p);
        cpa_commit();
    }

    for (int ch = 0; ch < NCH; ch++) {
        const int pre = ch + NSTG - 1;
        if (pre < NCH) ISSUE(pre, pre % NSTG);
        cpa_commit();
        cpa_wait<NSTG - 1>();
        __syncthreads();

        const int st = ch % NSTG;
        const float* As = sm + st * ASTAGE_F;
        const float* Bs = Bbase + st * BSTAGE_F;

#pragma unroll
        for (int ks = 0; ks < 4; ks++) {
            const int kc = ks * 8;
            // A fragments: 2 x LDS.64 per m-tile
            uint32_t ah[4][4];
#pragma unroll
            for (int mt = 0; mt < 4; mt++) {
                const int wl = wm * 64 + mt * 16;
                const uint32_t bXor = (uint32_t)(lc << 1);
                const uint32_t blk = (uint32_t)((wl >> 2) + (lr >> 1)) ^ bXor;
                const uint32_t fo  = (uint32_t)((lr & 1) * 2);
                // rows kc+lc and kc+4+lc
                float2 p01 = *(const float2*)(As + (kc + lc) * 128 + blk * 4 + fo);
                float2 p23 = *(const float2*)(As + (kc + 4 + lc) * 128 + blk * 4 + fo);
                ah[mt][0] = fbits(p01.x); ah[mt][1] = fbits(p01.y);
                ah[mt][2] = fbits(p23.x); ah[mt][3] = fbits(p23.y);
            }
            uint32_t bh[4][2];
#pragma unroll
            for (int nt = 0; nt < 4; nt++) {
                const int nb = wn * 32 + nt * 8;
                bh[nt][0] = fbits(Bs[(nb + lr) * 36 + kc + lc]);
                bh[nt][1] = fbits(Bs[(nb + lr) * 36 + kc + 4 + lc]);
            }
#pragma unroll
            for (int mt = 0; mt < 4; mt++)
#pragma unroll
                for (int nt = 0; nt < 4; nt++)
                    mma8(c[mt][nt], ah[mt], bh[nt]);
        }
        __syncthreads();
    }
#undef ISSUE

    // epilogue
    const float* bias = (mat == 0) ? bq : ((mat == 1) ? bk : bv);
    float* dst        = (mat == 0) ? g_q : ((mat == 1) ? g_k : g_v);
    const bool rqk    = (mat != 2);
#pragma unroll
    for (int mt = 0; mt < 4; mt++) {
        const int m = m0 + wm * 64 + mt * 16 + lr;
#pragma unroll
        for (int nt = 0; nt < 4; nt++) {
            const int n = n0 + wn * 32 + nt * 8 + 2 * lc;
            const int hh = n >> 6, d = n & 63;
            const float b0 = bias[n], b1 = bias[n + 1];
#pragma unroll
            for (int half = 0; half < 2; half++) {
                const int mm = m + half * 8;
                const int bi = mm >> 9, srow = mm & 511;
                float v0 = c[mt][nt][half * 2 + 0] + b0;
                float v1 = c[mt][nt][half * 2 + 1] + b1;
                if (rqk) { v0 = tf32r(v0); v1 = tf32r(v1); }
                float* o = dst + (((size_t)(bi * NH + hh)) * SEQ + srow) * DH + d;
                *(float2*)o = make_float2(v0, v1);
            }
        }
    }
}

// ---------------------------------------------------------------------------
// Power-law attention via mma.sync tf32 (unchanged from R5).
// ---------------------------------------------------------------------------
#define ATTN_SMEM ((128 * 68 + 64 * 68 + 64 * 72 + 128 * 68) * 4)

__global__ __launch_bounds__(256) void attn_kernel(
    const float* __restrict__ mask, float* __restrict__ out)
{
    extern __shared__ float sm[];
    float* Qs = sm;
    float* Ks = Qs + 128 * 68;
    float* Vs = Ks + 64 * 68;
    float* Us = Vs + 64 * 72;

    const int b  = blockIdx.z;
    const int h  = blockIdx.y;
    const int qt = blockIdx.x * 128;

    const float* Qg = g_q + (((size_t)(b * NH + h)) * SEQ + qt) * DH;
    const float* Kg = g_k + ((size_t)(b * NH + h)) * SEQ * DH;
    const float* Vg = g_v + ((size_t)(b * NH + h)) * SEQ * DH;

    const int tid  = threadIdx.x;
    const int lane = tid & 31;
    const int wid  = tid >> 5;
    const int wm   = wid >> 1;
    const int wn   = wid & 1;
    const int lr   = lane >> 2;
    const int lc   = lane & 3;

    {
        const int r = tid >> 1;
        const int sgm = (tid & 1) * 32;
        const float* src = Qg + (size_t)r * DH + sgm;
        float* dstq = &Qs[r * 68 + sgm];
#pragma unroll
        for (int i = 0; i < 8; i++)
            *(float4*)(dstq + i * 4) = *(const float4*)(src + i * 4);
    }

    float o[2][4][4];
#pragma unroll
    for (int i = 0; i < 2; i++)
#pragma unroll
        for (int j = 0; j < 4; j++)
#pragma unroll
            for (int q = 0; q < 4; q++) o[i][j][q] = 0.0f;
    float den[2][2] = {{0.0f, 0.0f}, {0.0f, 0.0f}};

    for (int kt = 0; kt < SEQ; kt += 64) {
        __syncthreads();
        {
            const int r = tid >> 2;
            const int sgm = (tid & 3) * 16;
            const float mv = mask[(size_t)b * SEQ + kt + r];
            const float* ksrc = Kg + (size_t)(kt + r) * DH + sgm;
            const float* vsrc = Vg + (size_t)(kt + r) * DH + sgm;
            float* kd = &Ks[r * 68 + sgm];
            float* vd = &Vs[r * 72 + sgm];
#pragma unroll
            for (int i = 0; i < 4; i++) {
                *(float4*)(kd + i * 4) = *(const float4*)(ksrc + i * 4);
                float4 vv = *(const float4*)(vsrc + i * 4);
                vd[i * 4 + 0] = tf32r(vv.x * mv);
                vd[i * 4 + 1] = tf32r(vv.y * mv);
                vd[i * 4 + 2] = tf32r(vv.z * mv);
                vd[i * 4 + 3] = tf32r(vv.w * mv);
            }
        }
        __syncthreads();

        float s[2][4][4];
#pragma unroll
        for (int i = 0; i < 2; i++)
#pragma unroll
            for (int j = 0; j < 4; j++)
#pragma unroll
                for (int q = 0; q < 4; q++) s[i][j][q] = 0.0f;

#pragma unroll
        for (int ks = 0; ks < 8; ks++) {
            const int kc = ks * 8;
            uint32_t a[2][4];
#pragma unroll
            for (int mt = 0; mt < 2; mt++) {
                const int rb = wm * 32 + mt * 16;
                a[mt][0] = fbits(Qs[(rb + lr) * 68 + kc + lc]);
                a[mt][1] = fbits(Qs[(rb + lr + 8) * 68 + kc + lc]);
                a[mt][2] = fbits(Qs[(rb + lr) * 68 + kc + 4 + lc]);
                a[mt][3] = fbits(Qs[(rb + lr + 8) * 68 + kc + 4 + lc]);
            }
            uint32_t bb[4][2];
#pragma unroll
            for (int nt = 0; nt < 4; nt++) {
                const int nb = wn * 32 + nt * 8;
                bb[nt][0] = fbits(Ks[(nb + lr) * 68 + kc + lc]);
                bb[nt][1] = fbits(Ks[(nb + lr) * 68 + kc + 4 + lc]);
            }
#pragma unroll
            for (int mt = 0; mt < 2; mt++)
#pragma unroll
                for (int nt = 0; nt < 4; nt++)
                    mma8(s[mt][nt], a[mt], bb[nt]);
        }
#pragma unroll
        for (int mt = 0; mt < 2; mt++) {
            const int rb = wm * 32 + mt * 16;
#pragma unroll
            for (int nt = 0; nt < 4; nt++) {
                const int cb = wn * 32 + nt * 8 + 2 * lc;
                float t0 = fmaf(s[mt][nt][0], 0.125f, 5.0f);
                float t1 = fmaf(s[mt][nt][1], 0.125f, 5.0f);
                float t2 = fmaf(s[mt][nt][2], 0.125f, 5.0f);
                float t3 = fmaf(s[mt][nt][3], 0.125f, 5.0f);
                *(float2*)&Us[(rb + lr) * 68 + cb] =
                    make_float2(tf32r(t0 * t0), tf32r(t1 * t1));
                *(float2*)&Us[(rb + lr + 8) * 68 + cb] =
                    make_float2(tf32r(t2 * t2), tf32r(t3 * t3));
            }
        }
        __syncthreads();

#pragma unroll
        for (int ks = 0; ks < 8; ks++) {
            const int kc = ks * 8;
            uint32_t a[2][4];
#pragma unroll
            for (int mt = 0; mt < 2; mt++) {
                const int rb = wm * 32 + mt * 16;
                float f0 = Us[(rb + lr) * 68 + kc + lc];
                float f1 = Us[(rb + lr + 8) * 68 + kc + lc];
                float f2 = Us[(rb + lr) * 68 + kc + 4 + lc];
                float f3 = Us[(rb + lr + 8) * 68 + kc + 4 + lc];
                den[mt][0] += f0 + f2;
                den[mt][1] += f1 + f3;
                a[mt][0] = fbits(f0); a[mt][1] = fbits(f1);
                a[mt][2] = fbits(f2); a[mt][3] = fbits(f3);
            }
            uint32_t bb[4][2];
#pragma unroll
            for (int nt = 0; nt < 4; nt++) {
                const int db = wn * 32 + nt * 8 + lr;
                bb[nt][0] = fbits(Vs[(kc + lc) * 72 + db]);
                bb[nt][1] = fbits(Vs[(kc + 4 + lc) * 72 + db]);
            }
#pragma unroll
            for (int mt = 0; mt < 2; mt++)
#pragma unroll
                for (int nt = 0; nt < 4; nt++)
                    mma8(o[mt][nt], a[mt], bb[nt]);
        }
    }

#pragma unroll
    for (int mt = 0; mt < 2; mt++)
#pragma unroll
        for (int j = 0; j < 2; j++) {
            float v = den[mt][j];
            v += __shfl_xor_sync(0xFFFFFFFFu, v, 1);
            v += __shfl_xor_sync(0xFFFFFFFFu, v, 2);
            den[mt][j] = v;
        }

#pragma unroll
    for (int mt = 0; mt < 2; mt++) {
        const float inv0 = 1.0f / (den[mt][0] + 1e-10f);
        const float inv1 = 1.0f / (den[mt][1] + 1e-10f);
        const int rb = qt + wm * 32 + mt * 16 + lr;
#pragma unroll
        for (int nt = 0; nt < 4; nt++) {
            const int d = wn * 32 + nt * 8 + 2 * lc;
            float* o0 = out + ((size_t)b * SEQ + rb) * DM + h * DH + d;
            float* o1 = out + ((size_t)b * SEQ + rb + 8) * DM + h * DH + d;
            *(float2*)o0 = make_float2(o[mt][nt][0] * inv0, o[mt][nt][1] * inv0);
            *(float2*)o1 = make_float2(o[mt][nt][2] * inv1, o[mt][nt][3] * inv1);
        }
    }
}

// ---------------------------------------------------------------------------
extern "C" void kernel_launch(void* const* d_in, const int* in_sizes, int n_in,
                              void* d_out, int out_size)
{
    const float* hidden = (const float*)d_in[0];
    const float* mask   = (const float*)d_in[1];
    const float* Wq     = (const float*)d_in[2];
    const float* bq     = (const float*)d_in[3];
    const float* Wk     = (const float*)d_in[4];
    const float* bk     = (const float*)d_in[5];
    const float* Wv     = (const float*)d_in[6];
    const float* bv     = (const float*)d_in[7];
    float* out = (float*)d_out;

    const int BS = in_sizes[1];
    const int B  = BS / SEQ;
    const int M  = BS;

    cudaFuncSetAttribute(qkv_gemm_kernel,
                         cudaFuncAttributeMaxDynamicSharedMemorySize, GEMM_SMEM);
    cudaFuncSetAttribute(attn_kernel,
                         cudaFuncAttributeMaxDynamicSharedMemorySize, ATTN_SMEM);

    dim3 gh(M / 32, DM / 32);
    htrans_kernel<<<gh, dim3(32, 8)>>>(hidden, M);

    dim3 gw(DM / 32, DM / 32, 3);
    wsplit_kernel<<<gw, dim3(32, 8)>>>(Wq, Wk, Wv);

    dim3 gm(M / 128, 18);
    qkv_gemm_kernel<<<gm, 256, GEMM_SMEM>>>(bq, bk, bv, M);

    dim3 g2(SEQ / 128, NH, B);
    attn_kernel<<<g2, 256, ATTN_SMEM>>>(mask, out);
}

// round 7
// speedup vs baseline: 4.2950x; 1.1456x over previous
#include <cuda_runtime.h>
#include <cstdint>

#define NH 12
#define DH 64
#define SEQ 512
#define DM 768
#define MAXB 32

typedef unsigned long long u64;

// ============================ PTX helpers ============================
__device__ __forceinline__ float tf32r(float x) {
    float r; asm("cvt.rna.tf32.f32 %0, %1;" : "=f"(r) : "f"(x)); return r;
}
__device__ __forceinline__ void mma8(float* c, const uint32_t* a, const uint32_t* b) {
    asm volatile(
        "mma.sync.aligned.m16n8k8.row.col.f32.tf32.tf32.f32 "
        "{%0,%1,%2,%3}, {%4,%5,%6,%7}, {%8,%9}, {%0,%1,%2,%3};"
        : "+f"(c[0]), "+f"(c[1]), "+f"(c[2]), "+f"(c[3])
        : "r"(a[0]), "r"(a[1]), "r"(a[2]), "r"(a[3]), "r"(b[0]), "r"(b[1]));
}
__device__ __forceinline__ uint32_t fbits(float x) { return __float_as_uint(x); }
__device__ __forceinline__ uint32_t smem_u32(const void* p) {
    uint32_t a;
    asm("{ .reg .u64 t; cvta.to.shared.u64 t, %1; cvt.u32.u64 %0, t; }" : "=r"(a) : "l"(p));
    return a;
}
__device__ __forceinline__ void cpa16(uint32_t s, const float* g) {
    asm volatile("cp.async.cg.shared.global [%0], [%1], 16;" :: "r"(s), "l"(g));
}
__device__ __forceinline__ void cpa_commit() {
    asm volatile("cp.async.commit_group;" ::: "memory");
}
template<int N>
__device__ __forceinline__ void cpa_wait() {
    asm volatile("cp.async.wait_group %0;" :: "n"(N) : "memory");
}

// d-perm within 8-groups: swap so (k, k+4) become adjacent
__device__ __forceinline__ int dperm(int d) {
    return (d & ~7) | (((d & 3) << 1) | ((d >> 2) & 1));
}

// ============================ device scratch ============================
__device__ float g_q[(size_t)MAXB * NH * SEQ * DH];     // tf32, d-permuted
__device__ float g_k[(size_t)MAXB * NH * SEQ * DH];     // tf32, d-permuted
__device__ float g_v[(size_t)MAXB * NH * SEQ * DH];     // tf32, natural d
__device__ float g_aht[(size_t)DM * MAXB * SEQ];        // hidden^T [k][m_perm], tf32
__device__ float g_wth[(size_t)3 * DM * DM];            // W^T [mat][n][k], tf32

// ---------------------------------------------------------------------------
__global__ void htrans_kernel(const float* __restrict__ h, int M) {
    __shared__ float t[32][33];
    const int m0 = blockIdx.x * 32, k0 = blockIdx.y * 32;
    const int tx = threadIdx.x, ty = threadIdx.y;
#pragma unroll
    for (int j = 0; j < 32; j += 8)
        t[ty + j][tx] = tf32r(h[(size_t)(m0 + ty + j) * DM + k0 + tx]);
    __syncthreads();
    const int m = m0 + tx;
    const int mp = (m & ~15) | (((m & 7) << 1) | ((m >> 3) & 1));
#pragma unroll
    for (int j = 0; j < 32; j += 8)
        g_aht[(size_t)(k0 + ty + j) * M + mp] = t[tx][ty + j];
}

__global__ void wsplit_kernel(const float* __restrict__ Wq,
                              const float* __restrict__ Wk,
                              const float* __restrict__ Wv) {
    __shared__ float th[32][33];
    int mat = blockIdx.z;
    const float* W = (mat == 0) ? Wq : ((mat == 1) ? Wk : Wv);
    int k0 = blockIdx.y * 32, n0 = blockIdx.x * 32;
    int tx = threadIdx.x, ty = threadIdx.y;
#pragma unroll
    for (int j = 0; j < 32; j += 8)
        th[ty + j][tx] = tf32r(W[(size_t)(k0 + ty + j) * DM + n0 + tx]);
    __syncthreads();
    float* oh = g_wth + (size_t)mat * DM * DM;
#pragma unroll
    for (int j = 0; j < 32; j += 8)
        oh[(size_t)(n0 + ty + j) * DM + k0 + tx] = th[tx][ty + j];
}

// ---------------------------------------------------------------------------
// Unified QKV GEMM (as R6) — epilogue: Q/K tf32+dperm scatter, V tf32.
// ---------------------------------------------------------------------------
#define ASTAGE_F 4096
#define BSTAGE_F (128 * 36)
#define NSTG 3
#define GEMM_SMEM ((NSTG * (ASTAGE_F + BSTAGE_F)) * 4)

__global__ __launch_bounds__(256) void qkv_gemm_kernel(
    const float* __restrict__ bq, const float* __restrict__ bk,
    const float* __restrict__ bv, int M)
{
    extern __shared__ float sm[];
    float* Bbase = sm + NSTG * ASTAGE_F;

    const int tid  = threadIdx.x;
    const int lane = tid & 31;
    const int wid  = tid >> 5;
    const int wm   = wid >> 2;
    const int wn   = wid & 3;
    const int lr   = lane >> 2;
    const int lc   = lane & 3;

    const int m0  = blockIdx.x * 128;
    const int yb  = blockIdx.y;
    const int mat = yb / 6;
    const int n0  = (yb % 6) * 128;

    const float* Wh = g_wth + (size_t)mat * DM * DM + (size_t)n0 * DM;

    const int ak   = tid >> 3;
    const int ams  = (tid & 7) * 16;
    const float* gA = g_aht + (size_t)ak * M + m0 + ams;
    const int brow = tid >> 1;
    const int bseg = (tid & 1) * 16;
    const float* gB = Wh + (size_t)brow * DM + bseg;

    const uint32_t sbA = smem_u32(sm);
    const uint32_t sbB = smem_u32(Bbase);
    const uint32_t aXor = (uint32_t)((ak & 3) << 1);
    const uint32_t aRow = (uint32_t)ak * 512;
    const uint32_t bOff = (uint32_t)(brow * 36 + bseg) * 4;

#define ISSUE(ch, st)                                                         \
    do {                                                                      \
        const float* _a = gA + (size_t)(ch) * 32 * M;                         \
        const float* _b = gB + (ch) * 32;                                     \
        uint32_t _sa = sbA + (st) * (ASTAGE_F * 4) + aRow;                    \
        uint32_t _sb = sbB + (st) * (BSTAGE_F * 4) + bOff;                    \
        _Pragma("unroll")                                                     \
        for (int _i = 0; _i < 4; _i++) {                                      \
            uint32_t _blk = (uint32_t)((ams >> 2) + _i) ^ aXor;               \
            cpa16(_sa + _blk * 16, _a + _i * 4);                              \
            cpa16(_sb + _i * 16, _b + _i * 4);                                \
        }                                                                     \
    } while (0)

    float c[4][4][4];
#pragma unroll
    for (int i = 0; i < 4; i++)
#pragma unroll
        for (int j = 0; j < 4; j++)
#pragma unroll
            for (int q = 0; q < 4; q++) c[i][j][q] = 0.0f;

    const int NCH = DM / 32;

#pragma unroll
    for (int p = 0; p < NSTG - 1; p++) {
        ISSUE(p, p);
        cpa_commit();
    }

    for (int ch = 0; ch < NCH; ch++) {
        const int pre = ch + NSTG - 1;
        if (pre < NCH) ISSUE(pre, pre % NSTG);
        cpa_commit();
        cpa_wait<NSTG - 1>();
        __syncthreads();

        const int st = ch % NSTG;
        const float* As = sm + st * ASTAGE_F;
        const float* Bs = Bbase + st * BSTAGE_F;

#pragma unroll
        for (int ks = 0; ks < 4; ks++) {
            const int kc = ks * 8;
            uint32_t ah[4][4];
#pragma unroll
            for (int mt = 0; mt < 4; mt++) {
                const int wl = wm * 64 + mt * 16;
                const uint32_t bXor = (uint32_t)(lc << 1);
                const uint32_t blk = (uint32_t)((wl >> 2) + (lr >> 1)) ^ bXor;
                const uint32_t fo  = (uint32_t)((lr & 1) * 2);
                float2 p01 = *(const float2*)(As + (kc + lc) * 128 + blk * 4 + fo);
                float2 p23 = *(const float2*)(As + (kc + 4 + lc) * 128 + blk * 4 + fo);
                ah[mt][0] = fbits(p01.x); ah[mt][1] = fbits(p01.y);
                ah[mt][2] = fbits(p23.x); ah[mt][3] = fbits(p23.y);
            }
            uint32_t bh[4][2];
#pragma unroll
            for (int nt = 0; nt < 4; nt++) {
                const int nb = wn * 32 + nt * 8;
                bh[nt][0] = fbits(Bs[(nb + lr) * 36 + kc + lc]);
                bh[nt][1] = fbits(Bs[(nb + lr) * 36 + kc + 4 + lc]);
            }
#pragma unroll
            for (int mt = 0; mt < 4; mt++)
#pragma unroll
                for (int nt = 0; nt < 4; nt++)
                    mma8(c[mt][nt], ah[mt], bh[nt]);
        }
        __syncthreads();
    }
#undef ISSUE

    // epilogue: Q/K -> tf32 + d-perm scatter; V -> tf32, natural layout
    const float* bias = (mat == 0) ? bq : ((mat == 1) ? bk : bv);
    float* dst        = (mat == 0) ? g_q : ((mat == 1) ? g_k : g_v);
    const bool rqk    = (mat != 2);
#pragma unroll
    for (int mt = 0; mt < 4; mt++) {
        const int m = m0 + wm * 64 + mt * 16 + lr;
#pragma unroll
        for (int nt = 0; nt < 4; nt++) {
            const int n = n0 + wn * 32 + nt * 8 + 2 * lc;
            const int hh = n >> 6, d = n & 63;
            const float b0 = bias[n], b1 = bias[n + 1];
#pragma unroll
            for (int half = 0; half < 2; half++) {
                const int mm = m + half * 8;
                const int bi = mm >> 9, srow = mm & 511;
                float v0 = tf32r(c[mt][nt][half * 2 + 0] + b0);
                float v1 = tf32r(c[mt][nt][half * 2 + 1] + b1);
                float* o = dst + (((size_t)(bi * NH + hh)) * SEQ + srow) * DH;
                if (rqk) {
                    o[dperm(d)]     = v0;
                    o[dperm(d + 1)] = v1;
                } else {
                    *(float2*)(o + d) = make_float2(v0, v1);
                }
            }
        }
    }
}

// ---------------------------------------------------------------------------
// Power-law attention: q-tile 128, key-tile 32, cp.async double-buffered K/V.
// Warps: 4(m) x 2(n). Phase1 frags via LDS.64 (d-perm layouts).
// Mask folded into phase2 V-fragments; den from pre-mask U.
// ---------------------------------------------------------------------------
#define KT 32
#define PADQ 72
#define PADKV 72
#define PADU 36
#define QS_F (128 * PADQ)          // 9216
#define KBUF_F (KT * PADKV)        // 2304
#define ATTN_SMEM ((QS_F + 4 * KBUF_F + 128 * PADU + 512) * 4)   // 94208 B

__global__ __launch_bounds__(256) void attn_kernel(
    const float* __restrict__ mask, float* __restrict__ out)
{
    extern __shared__ float sm[];
    float* Qs = sm;                         // [128][72]
    float* Ks = Qs + QS_F;                  // [2][32][72]
    float* Vs = Ks + 2 * KBUF_F;            // [2][32][72]
    float* Us = Vs + 2 * KBUF_F;            // [128][36]
    float* Ms = Us + 128 * PADU;            // [512]

    const int b  = blockIdx.z;
    const int h  = blockIdx.y;
    const int qt = blockIdx.x * 128;

    const float* Qg = g_q + (((size_t)(b * NH + h)) * SEQ + qt) * DH;
    const float* Kg = g_k + ((size_t)(b * NH + h)) * SEQ * DH;
    const float* Vg = g_v + ((size_t)(b * NH + h)) * SEQ * DH;

    const int tid  = threadIdx.x;
    const int lane = tid & 31;
    const int wid  = tid >> 5;
    const int wm   = wid >> 1;       // 0..3 : 32 q-rows
    const int wn   = wid & 1;        // 0..1
    const int lr   = lane >> 2;
    const int lc   = lane & 3;

    // cp.async K/V tile mapping: 32 rows x 64 floats; thread: row tid>>3, seg (tid&7)*8
    const int krow = tid >> 3;
    const int kseg = (tid & 7) * 8;
    const float* KgR = Kg + (size_t)krow * DH + kseg;
    const float* VgR = Vg + (size_t)krow * DH + kseg;
    const uint32_t sKs = smem_u32(Ks) + (uint32_t)(krow * PADKV + kseg) * 4;
    const uint32_t sVs = smem_u32(Vs) + (uint32_t)(krow * PADKV + kseg) * 4;

#define ISSKV(kt_, buf_)                                                      \
    do {                                                                      \
        const float* _k = KgR + (size_t)(kt_) * KT * DH;                      \
        const float* _v = VgR + (size_t)(kt_) * KT * DH;                      \
        uint32_t _ob = (uint32_t)(buf_) * (KBUF_F * 4);                       \
        cpa16(sKs + _ob, _k);      cpa16(sKs + _ob + 16, _k + 4);             \
        cpa16(sVs + _ob, _v);      cpa16(sVs + _ob + 16, _v + 4);             \
        cpa_commit();                                                         \
    } while (0)

    // prefetch tile 0
    ISSKV(0, 0);

    // load Q (raw; already tf32 + d-perm in gmem)
    {
        const int r = tid >> 1;
        const int sg = (tid & 1) * 32;
        const float* src = Qg + (size_t)r * DH + sg;
        float* dq = &Qs[r * PADQ + sg];
#pragma unroll
        for (int i = 0; i < 8; i++)
            *(float4*)(dq + i * 4) = *(const float4*)(src + i * 4);
    }
    // load mask row
    *(float2*)&Ms[tid * 2] = *(const float2*)(mask + (size_t)b * SEQ + tid * 2);

    float o[2][4][4];
#pragma unroll
    for (int i = 0; i < 2; i++)
#pragma unroll
        for (int j = 0; j < 4; j++)
#pragma unroll
            for (int q = 0; q < 4; q++) o[i][j][q] = 0.0f;
    float den[2][2] = {{0.0f, 0.0f}, {0.0f, 0.0f}};

    const int NKT = SEQ / KT;   // 16

    for (int kt = 0; kt < NKT; kt++) {
        const int buf = kt & 1;
        if (kt + 1 < NKT) {
            ISSKV(kt + 1, buf ^ 1);
            cpa_wait<1>();
        } else {
            cpa_wait<0>();
        }
        __syncthreads();

        const float* Kb = Ks + buf * KBUF_F;
        const float* Vb = Vs + buf * KBUF_F;

        // ---- phase 1: S = Q K^T (d = 8 ksteps), warp: 32 rows x 16 keys ----
        float s[2][2][4];
#pragma unroll
        for (int i = 0; i < 2; i++)
#pragma unroll
            for (int j = 0; j < 2; j++)
#pragma unroll
                for (int q = 0; q < 4; q++) s[i][j][q] = 0.0f;

#pragma unroll
        for (int ks = 0; ks < 8; ks++) {
            const int kc = ks * 8;
            uint32_t a[2][4];
#pragma unroll
            for (int mt = 0; mt < 2; mt++) {
                const int rb = wm * 32 + mt * 16;
                float2 p0 = *(const float2*)&Qs[(rb + lr) * PADQ + kc + 2 * lc];
                float2 p1 = *(const float2*)&Qs[(rb + lr + 8) * PADQ + kc + 2 * lc];
                a[mt][0] = fbits(p0.x); a[mt][1] = fbits(p1.x);
                a[mt][2] = fbits(p0.y); a[mt][3] = fbits(p1.y);
            }
            uint32_t bb[2][2];
#pragma unroll
            for (int nt = 0; nt < 2; nt++) {
                const int nb = wn * 16 + nt * 8;
                float2 q2 = *(const float2*)&Kb[(nb + lr) * PADKV + kc + 2 * lc];
                bb[nt][0] = fbits(q2.x); bb[nt][1] = fbits(q2.y);
            }
#pragma unroll
            for (int mt = 0; mt < 2; mt++)
#pragma unroll
                for (int nt = 0; nt < 2; nt++)
                    mma8(s[mt][nt], a[mt], bb[nt]);
        }
        // transform -> U (pre-mask, tf32-rounded)
#pragma unroll
        for (int mt = 0; mt < 2; mt++) {
            const int rb = wm * 32 + mt * 16;
#pragma unroll
            for (int nt = 0; nt < 2; nt++) {
                const int cb = wn * 16 + nt * 8 + 2 * lc;
                float t0 = fmaf(s[mt][nt][0], 0.125f, 5.0f);
                float t1 = fmaf(s[mt][nt][1], 0.125f, 5.0f);
                float t2 = fmaf(s[mt][nt][2], 0.125f, 5.0f);
                float t3 = fmaf(s[mt][nt][3], 0.125f, 5.0f);
                *(float2*)&Us[(rb + lr) * PADU + cb] =
                    make_float2(tf32r(t0 * t0), tf32r(t1 * t1));
                *(float2*)&Us[(rb + lr + 8) * PADU + cb] =
                    make_float2(tf32r(t2 * t2), tf32r(t3 * t3));
            }
        }
        __syncthreads();

        // ---- phase 2: O += U (mask∘V), keys = 4 ksteps; warp: 32 rows x 32 d
#pragma unroll
        for (int ks = 0; ks < 4; ks++) {
            const int kc = ks * 8;
            const float m0 = Ms[kt * KT + kc + lc];
            const float m1 = Ms[kt * KT + kc + 4 + lc];
            uint32_t a[2][4];
#pragma unroll
            for (int mt = 0; mt < 2; mt++) {
                const int rb = wm * 32 + mt * 16;
                float f0 = Us[(rb + lr) * PADU + kc + lc];
                float f1 = Us[(rb + lr + 8) * PADU + kc + lc];
                float f2 = Us[(rb + lr) * PADU + kc + 4 + lc];
                float f3 = Us[(rb + lr + 8) * PADU + kc + 4 + lc];
                den[mt][0] += f0 + f2;
                den[mt][1] += f1 + f3;
                a[mt][0] = fbits(f0); a[mt][1] = fbits(f1);
                a[mt][2] = fbits(f2); a[mt][3] = fbits(f3);
            }
            uint32_t bb[4][2];
#pragma unroll
            for (int nt = 0; nt < 4; nt++) {
                const int db = wn * 32 + nt * 8 + lr;
                bb[nt][0] = fbits(Vb[(kc + lc) * PADKV + db] * m0);
                bb[nt][1] = fbits(Vb[(kc + 4 + lc) * PADKV + db] * m1);
            }
#pragma unroll
            for (int mt = 0; mt < 2; mt++)
#pragma unroll
                for (int nt = 0; nt < 4; nt++)
                    mma8(o[mt][nt], a[mt], bb[nt]);
        }
        __syncthreads();   // protect Us + V buffer before next prefetch/store
    }
#undef ISSKV

    // quad-reduce den
#pragma unroll
    for (int mt = 0; mt < 2; mt++)
#pragma unroll
        for (int j = 0; j < 2; j++) {
            float v = den[mt][j];
            v += __shfl_xor_sync(0xFFFFFFFFu, v, 1);
            v += __shfl_xor_sync(0xFFFFFFFFu, v, 2);
            den[mt][j] = v;
        }

#pragma unroll
    for (int mt = 0; mt < 2; mt++) {
        const float inv0 = 1.0f / (den[mt][0] + 1e-10f);
        const float inv1 = 1.0f / (den[mt][1] + 1e-10f);
        const int rb = qt + wm * 32 + mt * 16 + lr;
#pragma unroll
        for (int nt = 0; nt < 4; nt++) {
            const int d = wn * 32 + nt * 8 + 2 * lc;
            float* o0 = out + ((size_t)b * SEQ + rb) * DM + h * DH + d;
            float* o1 = out + ((size_t)b * SEQ + rb + 8) * DM + h * DH + d;
            *(float2*)o0 = make_float2(o[mt][nt][0] * inv0, o[mt][nt][1] * inv0);
            *(float2*)o1 = make_float2(o[mt][nt][2] * inv1, o[mt][nt][3] * inv1);
        }
    }
}

// ---------------------------------------------------------------------------
extern "C" void kernel_launch(void* const* d_in, const int* in_sizes, int n_in,
                              void* d_out, int out_size)
{
    const float* hidden = (const float*)d_in[0];
    const float* mask   = (const float*)d_in[1];
    const float* Wq     = (const float*)d_in[2];
    const float* bq     = (const float*)d_in[3];
    const float* Wk     = (const float*)d_in[4];
    const float* bk     = (const float*)d_in[5];
    const float* Wv     = (const float*)d_in[6];
    const float* bv     = (const float*)d_in[7];
    float* out = (float*)d_out;

    const int BS = in_sizes[1];
    const int B  = BS / SEQ;
    const int M  = BS;

    cudaFuncSetAttribute(qkv_gemm_kernel,
                         cudaFuncAttributeMaxDynamicSharedMemorySize, GEMM_SMEM);
    cudaFuncSetAttribute(attn_kernel,
                         cudaFuncAttributeMaxDynamicSharedMemorySize, ATTN_SMEM);

    dim3 gh(M / 32, DM / 32);
    htrans_kernel<<<gh, dim3(32, 8)>>>(hidden, M);

    dim3 gw(DM / 32, DM / 32, 3);
    wsplit_kernel<<<gw, dim3(32, 8)>>>(Wq, Wk, Wv);

    dim3 gm(M / 128, 18);
    qkv_gemm_kernel<<<gm, 256, GEMM_SMEM>>>(bq, bk, bv, M);

    dim3 g2(SEQ / 128, NH, B);
    attn_kernel<<<g2, 256, ATTN_SMEM>>>(mask, out);
}